// round 7
// baseline (speedup 1.0000x reference)
#include <cuda_runtime.h>
#include <cuda_bf16.h>
#include <math.h>
#include <stdint.h>

#define BB 4
#define SS 2048
#define DD 1024
#define HH 16
#define DHH 64

// ---------------------------------------------------------------------------
// Scratch (allocation-free __device__ globals)
// ---------------------------------------------------------------------------
__device__ __nv_bfloat16 g_xhi[3 * BB * SS * DD];   // q/k/v inputs; slot0 reused for ctx
__device__ __nv_bfloat16 g_xlo[3 * BB * SS * DD];
__device__ __nv_bfloat16 g_whi[4 * DD * DD];        // Wq,Wk,Wv,Wo
__device__ __nv_bfloat16 g_wlo[4 * DD * DD];
__device__ __nv_bfloat16 g_qhi[BB * SS * DD];       // [B,H,S,DH]
__device__ __nv_bfloat16 g_qlo[BB * SS * DD];
__device__ __nv_bfloat16 g_khi[BB * SS * DD];       // [B,H,S,DH]
__device__ __nv_bfloat16 g_klo[BB * SS * DD];
__device__ __nv_bfloat16 g_vthi[BB * SS * DD];      // [B,H,DH,S]
__device__ __nv_bfloat16 g_vtlo[BB * SS * DD];

// ---------------------------------------------------------------------------
// helpers
// ---------------------------------------------------------------------------
__device__ __forceinline__ uint32_t smem_u32(const void* p) {
    uint32_t a;
    asm("{ .reg .u64 t; cvta.to.shared.u64 t, %1; cvt.u32.u64 %0, t; }"
        : "=r"(a) : "l"(p));
    return a;
}
__device__ __forceinline__ void cp16(uint32_t sdst, const void* gsrc) {
    asm volatile("cp.async.cg.shared.global [%0], [%1], 16;"
                 :: "r"(sdst), "l"(gsrc));
}
__device__ __forceinline__ void cp_commit() {
    asm volatile("cp.async.commit_group;");
}
template <int N>
__device__ __forceinline__ void cp_wait() {
    asm volatile("cp.async.wait_group %0;" :: "n"(N));
}
__device__ __forceinline__ void mma_bf16(float& c0, float& c1, float& c2, float& c3,
                                         uint32_t a0, uint32_t a1, uint32_t a2, uint32_t a3,
                                         uint32_t b0, uint32_t b1) {
    asm volatile(
        "mma.sync.aligned.m16n8k16.row.col.f32.bf16.bf16.f32 "
        "{%0,%1,%2,%3}, {%4,%5,%6,%7}, {%8,%9}, {%0,%1,%2,%3};"
        : "+f"(c0), "+f"(c1), "+f"(c2), "+f"(c3)
        : "r"(a0), "r"(a1), "r"(a2), "r"(a3), "r"(b0), "r"(b1));
}
__device__ __forceinline__ uint32_t pack_bf16x2(float lo, float hi) {
    uint32_t r;
    asm("cvt.rn.bf16x2.f32 %0, %1, %2;" : "=r"(r) : "f"(hi), "f"(lo));
    return r;
}

// ---------------------------------------------------------------------------
// fused fp32 -> bf16 hi/lo splits
// ---------------------------------------------------------------------------
__device__ __forceinline__ void split4(const float* __restrict__ x,
                                       __nv_bfloat16* __restrict__ hi,
                                       __nv_bfloat16* __restrict__ lo, int i)
{
    float4 v = ((const float4*)x)[i];
    __nv_bfloat16 h0 = __float2bfloat16_rn(v.x);
    __nv_bfloat16 h1 = __float2bfloat16_rn(v.y);
    __nv_bfloat16 h2 = __float2bfloat16_rn(v.z);
    __nv_bfloat16 h3 = __float2bfloat16_rn(v.w);
    __nv_bfloat16 l0 = __float2bfloat16_rn(v.x - __bfloat162float(h0));
    __nv_bfloat16 l1 = __float2bfloat16_rn(v.y - __bfloat162float(h1));
    __nv_bfloat16 l2 = __float2bfloat16_rn(v.z - __bfloat162float(h2));
    __nv_bfloat16 l3 = __float2bfloat16_rn(v.w - __bfloat162float(h3));
    __nv_bfloat162* hp = (__nv_bfloat162*)(hi + (size_t)i * 4);
    __nv_bfloat162* lp = (__nv_bfloat162*)(lo + (size_t)i * 4);
    hp[0] = __nv_bfloat162(h0, h1);
    hp[1] = __nv_bfloat162(h2, h3);
    lp[0] = __nv_bfloat162(l0, l1);
    lp[1] = __nv_bfloat162(l2, l3);
}

__global__ __launch_bounds__(256) void split_x3_kernel(
    const float* __restrict__ x0, const float* __restrict__ x1,
    const float* __restrict__ x2,
    __nv_bfloat16* __restrict__ hi, __nv_bfloat16* __restrict__ lo, int n4)
{
    const int z = blockIdx.y;
    const float* x = (z == 0) ? x0 : ((z == 1) ? x1 : x2);
    int i = blockIdx.x * blockDim.x + threadIdx.x;
    if (i >= n4) return;
    split4(x, hi + (size_t)z * n4 * 4, lo + (size_t)z * n4 * 4, i);
}

__global__ __launch_bounds__(256) void split_w4_kernel(
    const float* __restrict__ w0, const float* __restrict__ w1,
    const float* __restrict__ w2, const float* __restrict__ w3,
    __nv_bfloat16* __restrict__ hi, __nv_bfloat16* __restrict__ lo, int n4)
{
    const int z = blockIdx.y;
    const float* w = (z == 0) ? w0 : ((z == 1) ? w1 : ((z == 2) ? w2 : w3));
    int i = blockIdx.x * blockDim.x + threadIdx.x;
    if (i >= n4) return;
    split4(w, hi + (size_t)z * n4 * 4, lo + (size_t)z * n4 * 4, i);
}

// ---------------------------------------------------------------------------
// GEMM: 128-thread CTA, tile 64(M) x 128(N), BK=32, 2-stage cp.async.
// 4 warps, each warp 64x32 (all warps share the 64 M rows).
// 3 CTAs/SM (smem 61,440 B; regs capped via launch_bounds).
// ---------------------------------------------------------------------------
#define BK 32
#define NKC (DD / BK)
#define TSTRIDE 40
#define ATILE_B (64 * TSTRIDE * 2)    // 5120
#define BTILE_B (128 * TSTRIDE * 2)   // 10240
#define STAGE_B (2 * ATILE_B + 2 * BTILE_B)  // 30720
#define GEMM_SMEM (2 * STAGE_B)       // 61440
// stage offsets
#define OFF_AHI 0
#define OFF_ALO ATILE_B
#define OFF_BHI (2 * ATILE_B)
#define OFF_BLO (2 * ATILE_B + BTILE_B)

__device__ __forceinline__ void load_stage(
    uint32_t sbase, const __nv_bfloat16* Ahi, const __nv_bfloat16* Alo,
    const __nv_bfloat16* Whi, const __nv_bfloat16* Wlo,
    int bm, int bn, int k0, int tid)
{
#pragma unroll
    for (int p = 0; p < 2; p++) {  // A: 64 rows x 4 chunks = 256
        const int i = p * 128 + tid;
        const int r = i >> 2;
        const int c = i & 3;
        cp16(sbase + OFF_AHI + r * (TSTRIDE * 2) + c * 16,
             Ahi + (size_t)(bm + r) * DD + k0 + c * 8);
        cp16(sbase + OFF_ALO + r * (TSTRIDE * 2) + c * 16,
             Alo + (size_t)(bm + r) * DD + k0 + c * 8);
    }
#pragma unroll
    for (int p = 0; p < 4; p++) {  // B: 128 rows x 4 chunks = 512
        const int i = p * 128 + tid;
        const int r = i >> 2;
        const int c = i & 3;
        cp16(sbase + OFF_BHI + r * (TSTRIDE * 2) + c * 16,
             Whi + (size_t)(bn + r) * DD + k0 + c * 8);
        cp16(sbase + OFF_BLO + r * (TSTRIDE * 2) + c * 16,
             Wlo + (size_t)(bn + r) * DD + k0 + c * 8);
    }
    cp_commit();
}

__device__ __forceinline__ void gemm_mainloop(
    char* sm, uint32_t sb,
    const __nv_bfloat16* Ahi, const __nv_bfloat16* Alo,
    const __nv_bfloat16* Whi, const __nv_bfloat16* Wlo,
    int bm, int bn, int tid, int wn, int g, int t,
    float acc[4][4][4])
{
    load_stage(sb + 0 * STAGE_B, Ahi, Alo, Whi, Wlo, bm, bn, 0, tid);

    for (int kc = 0; kc < NKC; kc++) {
        if (kc + 1 < NKC) {
            load_stage(sb + ((kc + 1) & 1) * STAGE_B,
                       Ahi, Alo, Whi, Wlo, bm, bn, (kc + 1) * BK, tid);
            cp_wait<1>();
        } else {
            cp_wait<0>();
        }
        __syncthreads();

        const char* stg = sm + (kc & 1) * STAGE_B;
        const char* tAhi = stg + OFF_AHI;
        const char* tAlo = stg + OFF_ALO;
        const char* tWhi = stg + OFF_BHI;
        const char* tWlo = stg + OFF_BLO;

#pragma unroll
        for (int k16 = 0; k16 < 2; k16++) {
            const int k0 = k16 * 16;
            uint32_t ah[4][4], al[4][4], bh[4][2], bl[4][2];
#pragma unroll
            for (int mt = 0; mt < 4; mt++) {
                const int r0 = mt * 16 + g;
                const int cA = k0 + 2 * t;
                ah[mt][0] = *(const uint32_t*)(tAhi + ((r0)     * TSTRIDE + cA)     * 2);
                ah[mt][1] = *(const uint32_t*)(tAhi + ((r0 + 8) * TSTRIDE + cA)     * 2);
                ah[mt][2] = *(const uint32_t*)(tAhi + ((r0)     * TSTRIDE + cA + 8) * 2);
                ah[mt][3] = *(const uint32_t*)(tAhi + ((r0 + 8) * TSTRIDE + cA + 8) * 2);
                al[mt][0] = *(const uint32_t*)(tAlo + ((r0)     * TSTRIDE + cA)     * 2);
                al[mt][1] = *(const uint32_t*)(tAlo + ((r0 + 8) * TSTRIDE + cA)     * 2);
                al[mt][2] = *(const uint32_t*)(tAlo + ((r0)     * TSTRIDE + cA + 8) * 2);
                al[mt][3] = *(const uint32_t*)(tAlo + ((r0 + 8) * TSTRIDE + cA + 8) * 2);
            }
#pragma unroll
            for (int nt = 0; nt < 4; nt++) {
                const int nr = wn + nt * 8 + g;
                const int cB = k0 + 2 * t;
                bh[nt][0] = *(const uint32_t*)(tWhi + (nr * TSTRIDE + cB)     * 2);
                bh[nt][1] = *(const uint32_t*)(tWhi + (nr * TSTRIDE + cB + 8) * 2);
                bl[nt][0] = *(const uint32_t*)(tWlo + (nr * TSTRIDE + cB)     * 2);
                bl[nt][1] = *(const uint32_t*)(tWlo + (nr * TSTRIDE + cB + 8) * 2);
            }
#pragma unroll
            for (int mt = 0; mt < 4; mt++)
#pragma unroll
                for (int nt = 0; nt < 4; nt++) {
                    float* c = acc[mt][nt];
                    mma_bf16(c[0], c[1], c[2], c[3],
                             ah[mt][0], ah[mt][1], ah[mt][2], ah[mt][3],
                             bh[nt][0], bh[nt][1]);
                    mma_bf16(c[0], c[1], c[2], c[3],
                             ah[mt][0], ah[mt][1], ah[mt][2], ah[mt][3],
                             bl[nt][0], bl[nt][1]);
                    mma_bf16(c[0], c[1], c[2], c[3],
                             al[mt][0], al[mt][1], al[mt][2], al[mt][3],
                             bh[nt][0], bh[nt][1]);
                }
        }
        __syncthreads();
    }
}

// fused QKV projection GEMM: gridDim.z selects {Q, K, V}
__global__ __launch_bounds__(128, 3) void qkv_gemm_kernel(
    const __nv_bfloat16* __restrict__ xhi, const __nv_bfloat16* __restrict__ xlo,
    const __nv_bfloat16* __restrict__ whi, const __nv_bfloat16* __restrict__ wlo,
    const float* __restrict__ bq, const float* __restrict__ bk,
    const float* __restrict__ bv,
    __nv_bfloat16* __restrict__ qhi, __nv_bfloat16* __restrict__ qlo,
    __nv_bfloat16* __restrict__ khi, __nv_bfloat16* __restrict__ klo,
    __nv_bfloat16* __restrict__ vthi, __nv_bfloat16* __restrict__ vtlo)
{
    extern __shared__ char sm[];
    const uint32_t sb = smem_u32(sm);
    const int tid = threadIdx.x;
    const int wid = tid >> 5;
    const int lid = tid & 31;
    const int g = lid >> 2;
    const int t = lid & 3;
    const int bm = blockIdx.y * 64;
    const int bn = blockIdx.x * 128;
    const int wn = wid * 32;
    const int z = blockIdx.z;

    const size_t Msz = (size_t)BB * SS * DD;
    const __nv_bfloat16* Ahi = xhi + (size_t)z * Msz;
    const __nv_bfloat16* Alo = xlo + (size_t)z * Msz;
    const __nv_bfloat16* Whi = whi + (size_t)z * DD * DD;
    const __nv_bfloat16* Wlo = wlo + (size_t)z * DD * DD;
    const float* bias = (z == 0) ? bq : ((z == 1) ? bk : bv);
    __nv_bfloat16* Ohi = (z == 0) ? qhi : ((z == 1) ? khi : vthi);
    __nv_bfloat16* Olo = (z == 0) ? qlo : ((z == 1) ? klo : vtlo);

    float acc[4][4][4];
#pragma unroll
    for (int mt = 0; mt < 4; mt++)
#pragma unroll
        for (int nt = 0; nt < 4; nt++)
#pragma unroll
            for (int r = 0; r < 4; r++) acc[mt][nt][r] = 0.0f;

    gemm_mainloop(sm, sb, Ahi, Alo, Whi, Wlo, bm, bn, tid, wn, g, t, acc);

    const bool trans = (z == 2);
#pragma unroll
    for (int mt = 0; mt < 4; mt++) {
#pragma unroll
        for (int nt = 0; nt < 4; nt++) {
            const float* c = acc[mt][nt];
            const int n0 = bn + wn + nt * 8 + 2 * t;
            const float bia0 = __ldg(&bias[n0]);
            const float bia1 = __ldg(&bias[n0 + 1]);
#pragma unroll
            for (int half = 0; half < 2; half++) {
                const int m = bm + mt * 16 + g + half * 8;
                const float v0 = c[half * 2 + 0] + bia0;
                const float v1 = c[half * 2 + 1] + bia1;
                const int bidx = m >> 11;
                const int sidx = m & (SS - 1);
                const int h0 = n0 >> 6;
                const int dh = n0 & (DHH - 1);
                __nv_bfloat16 h_0 = __float2bfloat16_rn(v0);
                __nv_bfloat16 h_1 = __float2bfloat16_rn(v1);
                __nv_bfloat16 l_0 = __float2bfloat16_rn(v0 - __bfloat162float(h_0));
                __nv_bfloat16 l_1 = __float2bfloat16_rn(v1 - __bfloat162float(h_1));
                if (!trans) {
                    const size_t idx = (((size_t)bidx * HH + h0) * SS + sidx) * DHH + dh;
                    *(__nv_bfloat162*)(Ohi + idx) = __nv_bfloat162(h_0, h_1);
                    *(__nv_bfloat162*)(Olo + idx) = __nv_bfloat162(l_0, l_1);
                } else {
                    const size_t idx = (((size_t)bidx * HH + h0) * DHH + dh) * SS + sidx;
                    Ohi[idx] = h_0;
                    Ohi[idx + SS] = h_1;
                    Olo[idx] = l_0;
                    Olo[idx + SS] = l_1;
                }
            }
        }
    }
}

// O projection GEMM (fp32 row-major out)
__global__ __launch_bounds__(128, 3) void o_gemm_kernel(
    const __nv_bfloat16* __restrict__ Ahi, const __nv_bfloat16* __restrict__ Alo,
    const __nv_bfloat16* __restrict__ Whi, const __nv_bfloat16* __restrict__ Wlo,
    const float* __restrict__ bias, float* __restrict__ C)
{
    extern __shared__ char sm[];
    const uint32_t sb = smem_u32(sm);
    const int tid = threadIdx.x;
    const int wid = tid >> 5;
    const int lid = tid & 31;
    const int g = lid >> 2;
    const int t = lid & 3;
    const int bm = blockIdx.y * 64;
    const int bn = blockIdx.x * 128;
    const int wn = wid * 32;

    float acc[4][4][4];
#pragma unroll
    for (int mt = 0; mt < 4; mt++)
#pragma unroll
        for (int nt = 0; nt < 4; nt++)
#pragma unroll
            for (int r = 0; r < 4; r++) acc[mt][nt][r] = 0.0f;

    gemm_mainloop(sm, sb, Ahi, Alo, Whi, Wlo, bm, bn, tid, wn, g, t, acc);

#pragma unroll
    for (int mt = 0; mt < 4; mt++) {
#pragma unroll
        for (int nt = 0; nt < 4; nt++) {
            const float* c = acc[mt][nt];
            const int n0 = bn + wn + nt * 8 + 2 * t;
            const float bia0 = __ldg(&bias[n0]);
            const float bia1 = __ldg(&bias[n0 + 1]);
#pragma unroll
            for (int half = 0; half < 2; half++) {
                const int m = bm + mt * 16 + g + half * 8;
                C[(size_t)m * DD + n0]     = c[half * 2 + 0] + bia0;
                C[(size_t)m * DD + n0 + 1] = c[half * 2 + 1] + bia1;
            }
        }
    }
}

// ---------------------------------------------------------------------------
// Tensor-core flash attention; epilogue emits ctx as bf16 hi/lo directly
// ---------------------------------------------------------------------------
#define KSTR 72
#define FTILE_B (64 * KSTR * 2)
#define FSTAGE_B (4 * FTILE_B)
#define FLASH_SMEM (2 * FSTAGE_B)

__global__ __launch_bounds__(128) void flash_tc_kernel(
    const __nv_bfloat16* __restrict__ Qhi, const __nv_bfloat16* __restrict__ Qlo,
    const __nv_bfloat16* __restrict__ Khi, const __nv_bfloat16* __restrict__ Klo,
    const __nv_bfloat16* __restrict__ VThi, const __nv_bfloat16* __restrict__ VTlo,
    __nv_bfloat16* __restrict__ CtxHi, __nv_bfloat16* __restrict__ CtxLo)
{
    extern __shared__ char sm[];
    const uint32_t sb = smem_u32(sm);
    const int tid = threadIdx.x;
    const int wid = tid >> 5;
    const int lid = tid & 31;
    const int g = lid >> 2;
    const int t = lid & 3;
    const int qb = gridDim.x - 1 - blockIdx.x;
    const int bh = blockIdx.y;

    const size_t hoff = (size_t)bh * SS * DHH;
    const __nv_bfloat16* qhi = Qhi + hoff;
    const __nv_bfloat16* qlo = Qlo + hoff;
    const __nv_bfloat16* khi = Khi + hoff;
    const __nv_bfloat16* klo = Klo + hoff;
    const __nv_bfloat16* vthi = VThi + hoff;
    const __nv_bfloat16* vtlo = VTlo + hoff;

    const int qrow0 = qb * 64 + wid * 16;

    uint32_t qh[4][4], ql[4][4];
#pragma unroll
    for (int s = 0; s < 4; s++) {
        const int cA = s * 16 + 2 * t;
        qh[s][0] = *(const uint32_t*)(qhi + (size_t)(qrow0 + g)     * DHH + cA);
        qh[s][1] = *(const uint32_t*)(qhi + (size_t)(qrow0 + g + 8) * DHH + cA);
        qh[s][2] = *(const uint32_t*)(qhi + (size_t)(qrow0 + g)     * DHH + cA + 8);
        qh[s][3] = *(const uint32_t*)(qhi + (size_t)(qrow0 + g + 8) * DHH + cA + 8);
        ql[s][0] = *(const uint32_t*)(qlo + (size_t)(qrow0 + g)     * DHH + cA);
        ql[s][1] = *(const uint32_t*)(qlo + (size_t)(qrow0 + g + 8) * DHH + cA);
        ql[s][2] = *(const uint32_t*)(qlo + (size_t)(qrow0 + g)     * DHH + cA + 8);
        ql[s][3] = *(const uint32_t*)(qlo + (size_t)(qrow0 + g + 8) * DHH + cA + 8);
    }

    float oa[8][4];
#pragma unroll
    for (int j = 0; j < 8; j++)
#pragma unroll
        for (int r = 0; r < 4; r++) oa[j][r] = 0.0f;
    float mrun0 = -INFINITY, mrun1 = -INFINITY, lrun0 = 0.0f, lrun1 = 0.0f;

    auto load_kv = [&](int jb, int stage) {
        const uint32_t s0 = sb + stage * FSTAGE_B;
        const int kb = jb * 64;
#pragma unroll
        for (int p = 0; p < 4; p++) {
            const int i = p * 128 + tid;
            const int r = i >> 3;
            const int c = i & 7;
            const uint32_t d = r * (KSTR * 2) + c * 16;
            cp16(s0 + 0 * FTILE_B + d, khi  + (size_t)(kb + r) * DHH + c * 8);
            cp16(s0 + 1 * FTILE_B + d, klo  + (size_t)(kb + r) * DHH + c * 8);
            cp16(s0 + 2 * FTILE_B + d, vthi + (size_t)r * SS + kb + c * 8);
            cp16(s0 + 3 * FTILE_B + d, vtlo + (size_t)r * SS + kb + c * 8);
        }
    };

    load_kv(0, 0);
    cp_commit();

    const float scale = 0.125f;

    for (int jb = 0; jb <= qb; jb++) {
        const int s = jb & 1;
        if (jb < qb) {
            load_kv(jb + 1, s ^ 1);
            cp_commit();
            cp_wait<1>();
        } else {
            cp_wait<0>();
        }
        __syncthreads();

        const char* stg = sm + s * FSTAGE_B;
        const char* tKhi = stg + 0 * FTILE_B;
        const char* tKlo = stg + 1 * FTILE_B;
        const char* tVhi = stg + 2 * FTILE_B;
        const char* tVlo = stg + 3 * FTILE_B;

        float sacc[8][4];
#pragma unroll
        for (int j = 0; j < 8; j++)
#pragma unroll
            for (int r = 0; r < 4; r++) sacc[j][r] = 0.0f;

#pragma unroll
        for (int ks = 0; ks < 4; ks++) {
            const int cB = ks * 16 + 2 * t;
            uint32_t kbh[8][2], kbl[8][2];
#pragma unroll
            for (int j = 0; j < 8; j++) {
                const int nr = j * 8 + g;
                kbh[j][0] = *(const uint32_t*)(tKhi + (nr * KSTR + cB)     * 2);
                kbh[j][1] = *(const uint32_t*)(tKhi + (nr * KSTR + cB + 8) * 2);
                kbl[j][0] = *(const uint32_t*)(tKlo + (nr * KSTR + cB)     * 2);
                kbl[j][1] = *(const uint32_t*)(tKlo + (nr * KSTR + cB + 8) * 2);
            }
#pragma unroll
            for (int j = 0; j < 8; j++)
                mma_bf16(sacc[j][0], sacc[j][1], sacc[j][2], sacc[j][3],
                         qh[ks][0], qh[ks][1], qh[ks][2], qh[ks][3],
                         kbh[j][0], kbh[j][1]);
#pragma unroll
            for (int j = 0; j < 8; j++)
                mma_bf16(sacc[j][0], sacc[j][1], sacc[j][2], sacc[j][3],
                         qh[ks][0], qh[ks][1], qh[ks][2], qh[ks][3],
                         kbl[j][0], kbl[j][1]);
#pragma unroll
            for (int j = 0; j < 8; j++)
                mma_bf16(sacc[j][0], sacc[j][1], sacc[j][2], sacc[j][3],
                         ql[ks][0], ql[ks][1], ql[ks][2], ql[ks][3],
                         kbh[j][0], kbh[j][1]);
        }

        const int qg0 = qrow0 + g;
        const int qg1 = qrow0 + g + 8;
        if (jb == qb) {
            const int kbase = jb * 64;
#pragma unroll
            for (int j = 0; j < 8; j++) {
                const int c0 = kbase + j * 8 + 2 * t;
                const int c1 = c0 + 1;
                sacc[j][0] = (c0 > qg0) ? -1e30f : sacc[j][0] * scale;
                sacc[j][1] = (c1 > qg0) ? -1e30f : sacc[j][1] * scale;
                sacc[j][2] = (c0 > qg1) ? -1e30f : sacc[j][2] * scale;
                sacc[j][3] = (c1 > qg1) ? -1e30f : sacc[j][3] * scale;
            }
        } else {
#pragma unroll
            for (int j = 0; j < 8; j++)
#pragma unroll
                for (int r = 0; r < 4; r++) sacc[j][r] *= scale;
        }

        float mt0 = -INFINITY, mt1 = -INFINITY;
#pragma unroll
        for (int j = 0; j < 8; j++) {
            mt0 = fmaxf(mt0, fmaxf(sacc[j][0], sacc[j][1]));
            mt1 = fmaxf(mt1, fmaxf(sacc[j][2], sacc[j][3]));
        }
        mt0 = fmaxf(mt0, __shfl_xor_sync(0xffffffffu, mt0, 1));
        mt0 = fmaxf(mt0, __shfl_xor_sync(0xffffffffu, mt0, 2));
        mt1 = fmaxf(mt1, __shfl_xor_sync(0xffffffffu, mt1, 1));
        mt1 = fmaxf(mt1, __shfl_xor_sync(0xffffffffu, mt1, 2));
        const float mn0 = fmaxf(mrun0, mt0);
        const float mn1 = fmaxf(mrun1, mt1);
        const float al0 = __expf(mrun0 - mn0);
        const float al1 = __expf(mrun1 - mn1);
        float rs0 = 0.0f, rs1 = 0.0f;
#pragma unroll
        for (int j = 0; j < 8; j++) {
            sacc[j][0] = __expf(sacc[j][0] - mn0);
            sacc[j][1] = __expf(sacc[j][1] - mn0);
            sacc[j][2] = __expf(sacc[j][2] - mn1);
            sacc[j][3] = __expf(sacc[j][3] - mn1);
            rs0 += sacc[j][0] + sacc[j][1];
            rs1 += sacc[j][2] + sacc[j][3];
        }
        rs0 += __shfl_xor_sync(0xffffffffu, rs0, 1);
        rs0 += __shfl_xor_sync(0xffffffffu, rs0, 2);
        rs1 += __shfl_xor_sync(0xffffffffu, rs1, 1);
        rs1 += __shfl_xor_sync(0xffffffffu, rs1, 2);
        lrun0 = al0 * lrun0 + rs0;
        lrun1 = al1 * lrun1 + rs1;
        mrun0 = mn0;
        mrun1 = mn1;
#pragma unroll
        for (int j = 0; j < 8; j++) {
            oa[j][0] *= al0;
            oa[j][1] *= al0;
            oa[j][2] *= al1;
            oa[j][3] *= al1;
        }

#pragma unroll
        for (int ks = 0; ks < 4; ks++) {
            const int j0 = 2 * ks, j1 = 2 * ks + 1;
            uint32_t pah[4], pal[4];
            {
                uint32_t h;
                __nv_bfloat162 hb;
                h = pack_bf16x2(sacc[j0][0], sacc[j0][1]);
                hb = *(__nv_bfloat162*)&h;
                pah[0] = h;
                pal[0] = pack_bf16x2(sacc[j0][0] - __bfloat162float(hb.x),
                                     sacc[j0][1] - __bfloat162float(hb.y));
                h = pack_bf16x2(sacc[j0][2], sacc[j0][3]);
                hb = *(__nv_bfloat162*)&h;
                pah[1] = h;
                pal[1] = pack_bf16x2(sacc[j0][2] - __bfloat162float(hb.x),
                                     sacc[j0][3] - __bfloat162float(hb.y));
                h = pack_bf16x2(sacc[j1][0], sacc[j1][1]);
                hb = *(__nv_bfloat162*)&h;
                pah[2] = h;
                pal[2] = pack_bf16x2(sacc[j1][0] - __bfloat162float(hb.x),
                                     sacc[j1][1] - __bfloat162float(hb.y));
                h = pack_bf16x2(sacc[j1][2], sacc[j1][3]);
                hb = *(__nv_bfloat162*)&h;
                pah[3] = h;
                pal[3] = pack_bf16x2(sacc[j1][2] - __bfloat162float(hb.x),
                                     sacc[j1][3] - __bfloat162float(hb.y));
            }
            uint32_t vh[8][2], vl[8][2];
#pragma unroll
            for (int jd = 0; jd < 8; jd++) {
                const int nr = jd * 8 + g;
                const int cB = ks * 16 + 2 * t;
                vh[jd][0] = *(const uint32_t*)(tVhi + (nr * KSTR + cB)     * 2);
                vh[jd][1] = *(const uint32_t*)(tVhi + (nr * KSTR + cB + 8) * 2);
                vl[jd][0] = *(const uint32_t*)(tVlo + (nr * KSTR + cB)     * 2);
                vl[jd][1] = *(const uint32_t*)(tVlo + (nr * KSTR + cB + 8) * 2);
            }
#pragma unroll
            for (int jd = 0; jd < 8; jd++)
                mma_bf16(oa[jd][0], oa[jd][1], oa[jd][2], oa[jd][3],
                         pah[0], pah[1], pah[2], pah[3], vh[jd][0], vh[jd][1]);
#pragma unroll
            for (int jd = 0; jd < 8; jd++)
                mma_bf16(oa[jd][0], oa[jd][1], oa[jd][2], oa[jd][3],
                         pah[0], pah[1], pah[2], pah[3], vl[jd][0], vl[jd][1]);
#pragma unroll
            for (int jd = 0; jd < 8; jd++)
                mma_bf16(oa[jd][0], oa[jd][1], oa[jd][2], oa[jd][3],
                         pal[0], pal[1], pal[2], pal[3], vh[jd][0], vh[jd][1]);
        }
        __syncthreads();
    }

    // finalize: ctx as bf16 hi/lo (identical arithmetic to fp32-store + split)
    const int b = bh >> 4;
    const int h = bh & 15;
    const float inv0 = 1.0f / lrun0;
    const float inv1 = 1.0f / lrun1;
#pragma unroll
    for (int jd = 0; jd < 8; jd++) {
        const int dh = jd * 8 + 2 * t;
        const float v00 = oa[jd][0] * inv0;
        const float v01 = oa[jd][1] * inv0;
        const float v10 = oa[jd][2] * inv1;
        const float v11 = oa[jd][3] * inv1;
        __nv_bfloat16 h00 = __float2bfloat16_rn(v00);
        __nv_bfloat16 h01 = __float2bfloat16_rn(v01);
        __nv_bfloat16 h10 = __float2bfloat16_rn(v10);
        __nv_bfloat16 h11 = __float2bfloat16_rn(v11);
        __nv_bfloat16 l00 = __float2bfloat16_rn(v00 - __bfloat162float(h00));
        __nv_bfloat16 l01 = __float2bfloat16_rn(v01 - __bfloat162float(h01));
        __nv_bfloat16 l10 = __float2bfloat16_rn(v10 - __bfloat162float(h10));
        __nv_bfloat16 l11 = __float2bfloat16_rn(v11 - __bfloat162float(h11));
        const size_t idx0 = ((size_t)b * SS + qrow0 + g)     * DD + h * DHH + dh;
        const size_t idx1 = ((size_t)b * SS + qrow0 + g + 8) * DD + h * DHH + dh;
        *(__nv_bfloat162*)(CtxHi + idx0) = __nv_bfloat162(h00, h01);
        *(__nv_bfloat162*)(CtxLo + idx0) = __nv_bfloat162(l00, l01);
        *(__nv_bfloat162*)(CtxHi + idx1) = __nv_bfloat162(h10, h11);
        *(__nv_bfloat162*)(CtxLo + idx1) = __nv_bfloat162(l10, l11);
    }
}

// ---------------------------------------------------------------------------
// Launch
// ---------------------------------------------------------------------------
extern "C" void kernel_launch(void* const* d_in, const int* in_sizes, int n_in,
                              void* d_out, int out_size)
{
    const float* query = (const float*)d_in[0];
    const float* key_i = (const float*)d_in[1];
    const float* value = (const float*)d_in[2];
    const float* Wq = (const float*)d_in[4];
    const float* bq = (const float*)d_in[5];
    const float* Wk = (const float*)d_in[6];
    const float* bk = (const float*)d_in[7];
    const float* Wv = (const float*)d_in[8];
    const float* bv = (const float*)d_in[9];
    const float* Wo = (const float*)d_in[10];
    const float* bo = (const float*)d_in[11];
    float* out = (float*)d_out;

    __nv_bfloat16 *xhi, *xlo, *whi, *wlo;
    __nv_bfloat16 *qhi, *qlo, *khi, *klo, *vthi, *vtlo;
    cudaGetSymbolAddress((void**)&xhi, g_xhi);
    cudaGetSymbolAddress((void**)&xlo, g_xlo);
    cudaGetSymbolAddress((void**)&whi, g_whi);
    cudaGetSymbolAddress((void**)&wlo, g_wlo);
    cudaGetSymbolAddress((void**)&qhi, g_qhi);
    cudaGetSymbolAddress((void**)&qlo, g_qlo);
    cudaGetSymbolAddress((void**)&khi, g_khi);
    cudaGetSymbolAddress((void**)&klo, g_klo);
    cudaGetSymbolAddress((void**)&vthi, g_vthi);
    cudaGetSymbolAddress((void**)&vtlo, g_vtlo);

    const int M = BB * SS;
    const int nX4 = M * DD / 4;
    const int nW4 = DD * DD / 4;

    cudaFuncSetAttribute(qkv_gemm_kernel,
                         cudaFuncAttributeMaxDynamicSharedMemorySize, GEMM_SMEM);
    cudaFuncSetAttribute(o_gemm_kernel,
                         cudaFuncAttributeMaxDynamicSharedMemorySize, GEMM_SMEM);
    cudaFuncSetAttribute(flash_tc_kernel,
                         cudaFuncAttributeMaxDynamicSharedMemorySize, FLASH_SMEM);

    // splits
    split_x3_kernel<<<dim3((nX4 + 255) / 256, 3), 256>>>(
        query, key_i, value, xhi, xlo, nX4);
    split_w4_kernel<<<dim3((nW4 + 255) / 256, 4), 256>>>(
        Wq, Wk, Wv, Wo, whi, wlo, nW4);

    // fused QKV projections (z = 0,1,2), 64x128 tiles
    qkv_gemm_kernel<<<dim3(DD / 128, M / 64, 3), 128, GEMM_SMEM>>>(
        xhi, xlo, whi, wlo, bq, bk, bv,
        qhi, qlo, khi, klo, vthi, vtlo);

    // tensor-core flash attention -> ctx bf16 hi/lo (reuse x slot 0)
    flash_tc_kernel<<<dim3(SS / 64, BB * HH), 128, FLASH_SMEM>>>(
        qhi, qlo, khi, klo, vthi, vtlo, xhi, xlo);

    // O projection
    o_gemm_kernel<<<dim3(DD / 128, M / 64), 128, GEMM_SMEM>>>(
        xhi, xlo, whi + (size_t)3 * DD * DD, wlo + (size_t)3 * DD * DD, bo, out);
}

// round 8
// speedup vs baseline: 1.5427x; 1.5427x over previous
#include <cuda_runtime.h>
#include <cuda_bf16.h>
#include <math.h>
#include <stdint.h>

#define BB 4
#define SS 2048
#define DD 1024
#define HH 16
#define DHH 64

// ---------------------------------------------------------------------------
// Scratch (allocation-free __device__ globals)
// ---------------------------------------------------------------------------
__device__ float g_ctx[BB * SS * DD];
__device__ __nv_bfloat16 g_xhi[3 * BB * SS * DD];
__device__ __nv_bfloat16 g_xlo[3 * BB * SS * DD];
__device__ __nv_bfloat16 g_whi[4 * DD * DD];
__device__ __nv_bfloat16 g_wlo[4 * DD * DD];
__device__ __nv_bfloat16 g_qhi[BB * SS * DD];       // [B,H,S,DH]
__device__ __nv_bfloat16 g_qlo[BB * SS * DD];
__device__ __nv_bfloat16 g_khi[BB * SS * DD];       // [B,H,S,DH]
__device__ __nv_bfloat16 g_klo[BB * SS * DD];
__device__ __nv_bfloat16 g_vthi[BB * SS * DD];      // [B,H,DH,S]
__device__ __nv_bfloat16 g_vtlo[BB * SS * DD];

// ---------------------------------------------------------------------------
// helpers
// ---------------------------------------------------------------------------
__device__ __forceinline__ uint32_t smem_u32(const void* p) {
    uint32_t a;
    asm("{ .reg .u64 t; cvta.to.shared.u64 t, %1; cvt.u32.u64 %0, t; }"
        : "=r"(a) : "l"(p));
    return a;
}
__device__ __forceinline__ void cp16(uint32_t sdst, const void* gsrc) {
    asm volatile("cp.async.cg.shared.global [%0], [%1], 16;"
                 :: "r"(sdst), "l"(gsrc));
}
__device__ __forceinline__ void cp_commit() {
    asm volatile("cp.async.commit_group;");
}
template <int N>
__device__ __forceinline__ void cp_wait() {
    asm volatile("cp.async.wait_group %0;" :: "n"(N));
}
__device__ __forceinline__ void mma_bf16(float& c0, float& c1, float& c2, float& c3,
                                         uint32_t a0, uint32_t a1, uint32_t a2, uint32_t a3,
                                         uint32_t b0, uint32_t b1) {
    asm volatile(
        "mma.sync.aligned.m16n8k16.row.col.f32.bf16.bf16.f32 "
        "{%0,%1,%2,%3}, {%4,%5,%6,%7}, {%8,%9}, {%0,%1,%2,%3};"
        : "+f"(c0), "+f"(c1), "+f"(c2), "+f"(c3)
        : "r"(a0), "r"(a1), "r"(a2), "r"(a3), "r"(b0), "r"(b1));
}
__device__ __forceinline__ uint32_t pack_bf16x2(float lo, float hi) {
    uint32_t r;
    asm("cvt.rn.bf16x2.f32 %0, %1, %2;" : "=r"(r) : "f"(hi), "f"(lo));
    return r;
}

// ---------------------------------------------------------------------------
// fused fp32 -> bf16 hi/lo splits
// ---------------------------------------------------------------------------
__device__ __forceinline__ void split4(const float* __restrict__ x,
                                       __nv_bfloat16* __restrict__ hi,
                                       __nv_bfloat16* __restrict__ lo, int i)
{
    float4 v = ((const float4*)x)[i];
    __nv_bfloat16 h0 = __float2bfloat16_rn(v.x);
    __nv_bfloat16 h1 = __float2bfloat16_rn(v.y);
    __nv_bfloat16 h2 = __float2bfloat16_rn(v.z);
    __nv_bfloat16 h3 = __float2bfloat16_rn(v.w);
    __nv_bfloat16 l0 = __float2bfloat16_rn(v.x - __bfloat162float(h0));
    __nv_bfloat16 l1 = __float2bfloat16_rn(v.y - __bfloat162float(h1));
    __nv_bfloat16 l2 = __float2bfloat16_rn(v.z - __bfloat162float(h2));
    __nv_bfloat16 l3 = __float2bfloat16_rn(v.w - __bfloat162float(h3));
    __nv_bfloat162* hp = (__nv_bfloat162*)(hi + (size_t)i * 4);
    __nv_bfloat162* lp = (__nv_bfloat162*)(lo + (size_t)i * 4);
    hp[0] = __nv_bfloat162(h0, h1);
    hp[1] = __nv_bfloat162(h2, h3);
    lp[0] = __nv_bfloat162(l0, l1);
    lp[1] = __nv_bfloat162(l2, l3);
}

__global__ __launch_bounds__(256) void split_x3_kernel(
    const float* __restrict__ x0, const float* __restrict__ x1,
    const float* __restrict__ x2,
    __nv_bfloat16* __restrict__ hi, __nv_bfloat16* __restrict__ lo, int n4)
{
    const int z = blockIdx.y;
    const float* x = (z == 0) ? x0 : ((z == 1) ? x1 : x2);
    int i = blockIdx.x * blockDim.x + threadIdx.x;
    if (i >= n4) return;
    split4(x, hi + (size_t)z * n4 * 4, lo + (size_t)z * n4 * 4, i);
}

__global__ __launch_bounds__(256) void split_w4_kernel(
    const float* __restrict__ w0, const float* __restrict__ w1,
    const float* __restrict__ w2, const float* __restrict__ w3,
    __nv_bfloat16* __restrict__ hi, __nv_bfloat16* __restrict__ lo, int n4)
{
    const int z = blockIdx.y;
    const float* w = (z == 0) ? w0 : ((z == 1) ? w1 : ((z == 2) ? w2 : w3));
    int i = blockIdx.x * blockDim.x + threadIdx.x;
    if (i >= n4) return;
    split4(w, hi + (size_t)z * n4 * 4, lo + (size_t)z * n4 * 4, i);
}

__global__ __launch_bounds__(256) void split_kernel(
    const float* __restrict__ x, __nv_bfloat16* __restrict__ hi,
    __nv_bfloat16* __restrict__ lo, int n4)
{
    int i = blockIdx.x * blockDim.x + threadIdx.x;
    if (i >= n4) return;
    split4(x, hi, lo, i);
}

// ---------------------------------------------------------------------------
// GEMM: CTA 128x128, 256 thr (8 warps, 2M x 4N), BK=64, 3-stage cp.async.
// smem row stride 72 bf16 (144 B) -- conflict-free (same layout as flash).
// ---------------------------------------------------------------------------
#define BK 64
#define NKC (DD / BK)                 // 16 chunks
#define TSTRIDE 72
#define TILE_B (128 * TSTRIDE * 2)    // 18432
#define STAGE_B (4 * TILE_B)          // 73728
#define NSTAGE 3
#define GEMM_SMEM (NSTAGE * STAGE_B)  // 221184

__device__ __forceinline__ void load_tile_async(
    uint32_t sbase, const __nv_bfloat16* __restrict__ src,
    int row_base, int k0, int tid)
{
#pragma unroll
    for (int p = 0; p < 4; p++) {
        const int i = p * 256 + tid;    // 0..1023
        const int r = i >> 3;           // 0..127
        const int c = i & 7;            // 16B unit (8 bf16)
        cp16(sbase + r * (TSTRIDE * 2) + c * 16,
             src + (size_t)(row_base + r) * DD + k0 + c * 8);
    }
}

__device__ __forceinline__ void load_stage(
    uint32_t sbase, const __nv_bfloat16* Ahi, const __nv_bfloat16* Alo,
    const __nv_bfloat16* Whi, const __nv_bfloat16* Wlo,
    int bm, int bn, int k0, int tid)
{
    load_tile_async(sbase + 0 * TILE_B, Ahi, bm, k0, tid);
    load_tile_async(sbase + 1 * TILE_B, Alo, bm, k0, tid);
    load_tile_async(sbase + 2 * TILE_B, Whi, bn, k0, tid);
    load_tile_async(sbase + 3 * TILE_B, Wlo, bn, k0, tid);
    cp_commit();
}

__device__ __forceinline__ void gemm_mainloop(
    char* sm, uint32_t sb,
    const __nv_bfloat16* Ahi, const __nv_bfloat16* Alo,
    const __nv_bfloat16* Whi, const __nv_bfloat16* Wlo,
    int bm, int bn, int tid, int wm, int wn, int g, int t,
    float acc[4][4][4])
{
    load_stage(sb + 0 * STAGE_B, Ahi, Alo, Whi, Wlo, bm, bn, 0, tid);
    load_stage(sb + 1 * STAGE_B, Ahi, Alo, Whi, Wlo, bm, bn, BK, tid);

    for (int kc = 0; kc < NKC; kc++) {
        if (kc + 2 < NKC) {
            load_stage(sb + ((kc + 2) % NSTAGE) * STAGE_B,
                       Ahi, Alo, Whi, Wlo, bm, bn, (kc + 2) * BK, tid);
            cp_wait<2>();
        } else if (kc + 1 < NKC) {
            cp_wait<1>();
        } else {
            cp_wait<0>();
        }
        __syncthreads();

        const char* stg = sm + (kc % NSTAGE) * STAGE_B;
        const char* tAhi = stg + 0 * TILE_B;
        const char* tAlo = stg + 1 * TILE_B;
        const char* tWhi = stg + 2 * TILE_B;
        const char* tWlo = stg + 3 * TILE_B;

#pragma unroll
        for (int k16 = 0; k16 < 4; k16++) {
            const int k0 = k16 * 16;
            uint32_t ah[4][4], al[4][4], bh[4][2], bl[4][2];
#pragma unroll
            for (int mt = 0; mt < 4; mt++) {
                const int r0 = wm + mt * 16 + g;
                const int cA = k0 + 2 * t;
                ah[mt][0] = *(const uint32_t*)(tAhi + ((r0)     * TSTRIDE + cA)     * 2);
                ah[mt][1] = *(const uint32_t*)(tAhi + ((r0 + 8) * TSTRIDE + cA)     * 2);
                ah[mt][2] = *(const uint32_t*)(tAhi + ((r0)     * TSTRIDE + cA + 8) * 2);
                ah[mt][3] = *(const uint32_t*)(tAhi + ((r0 + 8) * TSTRIDE + cA + 8) * 2);
                al[mt][0] = *(const uint32_t*)(tAlo + ((r0)     * TSTRIDE + cA)     * 2);
                al[mt][1] = *(const uint32_t*)(tAlo + ((r0 + 8) * TSTRIDE + cA)     * 2);
                al[mt][2] = *(const uint32_t*)(tAlo + ((r0)     * TSTRIDE + cA + 8) * 2);
                al[mt][3] = *(const uint32_t*)(tAlo + ((r0 + 8) * TSTRIDE + cA + 8) * 2);
            }
#pragma unroll
            for (int nt = 0; nt < 4; nt++) {
                const int nr = wn + nt * 8 + g;
                const int cB = k0 + 2 * t;
                bh[nt][0] = *(const uint32_t*)(tWhi + (nr * TSTRIDE + cB)     * 2);
                bh[nt][1] = *(const uint32_t*)(tWhi + (nr * TSTRIDE + cB + 8) * 2);
                bl[nt][0] = *(const uint32_t*)(tWlo + (nr * TSTRIDE + cB)     * 2);
                bl[nt][1] = *(const uint32_t*)(tWlo + (nr * TSTRIDE + cB + 8) * 2);
            }
#pragma unroll
            for (int mt = 0; mt < 4; mt++)
#pragma unroll
                for (int nt = 0; nt < 4; nt++) {
                    float* c = acc[mt][nt];
                    mma_bf16(c[0], c[1], c[2], c[3],
                             ah[mt][0], ah[mt][1], ah[mt][2], ah[mt][3],
                             bh[nt][0], bh[nt][1]);
                    mma_bf16(c[0], c[1], c[2], c[3],
                             ah[mt][0], ah[mt][1], ah[mt][2], ah[mt][3],
                             bl[nt][0], bl[nt][1]);
                    mma_bf16(c[0], c[1], c[2], c[3],
                             al[mt][0], al[mt][1], al[mt][2], al[mt][3],
                             bh[nt][0], bh[nt][1]);
                }
        }
        __syncthreads();
    }
}

// fused QKV projection GEMM: gridDim.z selects {Q, K, V}
__global__ __launch_bounds__(256) void qkv_gemm_kernel(
    const __nv_bfloat16* __restrict__ xhi, const __nv_bfloat16* __restrict__ xlo,
    const __nv_bfloat16* __restrict__ whi, const __nv_bfloat16* __restrict__ wlo,
    const float* __restrict__ bq, const float* __restrict__ bk,
    const float* __restrict__ bv,
    __nv_bfloat16* __restrict__ qhi, __nv_bfloat16* __restrict__ qlo,
    __nv_bfloat16* __restrict__ khi, __nv_bfloat16* __restrict__ klo,
    __nv_bfloat16* __restrict__ vthi, __nv_bfloat16* __restrict__ vtlo)
{
    extern __shared__ char sm[];
    const uint32_t sb = smem_u32(sm);
    const int tid = threadIdx.x;
    const int wid = tid >> 5;
    const int lid = tid & 31;
    const int g = lid >> 2;
    const int t = lid & 3;
    const int bm = blockIdx.y * 128;
    const int bn = blockIdx.x * 128;
    const int wm = (wid & 1) * 64;
    const int wn = (wid >> 1) * 32;
    const int z = blockIdx.z;

    const size_t Msz = (size_t)BB * SS * DD;
    const __nv_bfloat16* Ahi = xhi + (size_t)z * Msz;
    const __nv_bfloat16* Alo = xlo + (size_t)z * Msz;
    const __nv_bfloat16* Whi = whi + (size_t)z * DD * DD;
    const __nv_bfloat16* Wlo = wlo + (size_t)z * DD * DD;
    const float* bias = (z == 0) ? bq : ((z == 1) ? bk : bv);
    __nv_bfloat16* Ohi = (z == 0) ? qhi : ((z == 1) ? khi : vthi);
    __nv_bfloat16* Olo = (z == 0) ? qlo : ((z == 1) ? klo : vtlo);

    float acc[4][4][4];
#pragma unroll
    for (int mt = 0; mt < 4; mt++)
#pragma unroll
        for (int nt = 0; nt < 4; nt++)
#pragma unroll
            for (int r = 0; r < 4; r++) acc[mt][nt][r] = 0.0f;

    gemm_mainloop(sm, sb, Ahi, Alo, Whi, Wlo, bm, bn, tid, wm, wn, g, t, acc);

    const bool trans = (z == 2);
#pragma unroll
    for (int mt = 0; mt < 4; mt++) {
#pragma unroll
        for (int nt = 0; nt < 4; nt++) {
            const float* c = acc[mt][nt];
            const int n0 = bn + wn + nt * 8 + 2 * t;
            const float bia0 = __ldg(&bias[n0]);
            const float bia1 = __ldg(&bias[n0 + 1]);
#pragma unroll
            for (int half = 0; half < 2; half++) {
                const int m = bm + wm + mt * 16 + g + half * 8;
                const float v0 = c[half * 2 + 0] + bia0;
                const float v1 = c[half * 2 + 1] + bia1;
                const int bidx = m >> 11;
                const int sidx = m & (SS - 1);
                const int h0 = n0 >> 6;
                const int dh = n0 & (DHH - 1);
                __nv_bfloat16 h_0 = __float2bfloat16_rn(v0);
                __nv_bfloat16 h_1 = __float2bfloat16_rn(v1);
                __nv_bfloat16 l_0 = __float2bfloat16_rn(v0 - __bfloat162float(h_0));
                __nv_bfloat16 l_1 = __float2bfloat16_rn(v1 - __bfloat162float(h_1));
                if (!trans) {
                    const size_t idx = (((size_t)bidx * HH + h0) * SS + sidx) * DHH + dh;
                    *(__nv_bfloat162*)(Ohi + idx) = __nv_bfloat162(h_0, h_1);
                    *(__nv_bfloat162*)(Olo + idx) = __nv_bfloat162(l_0, l_1);
                } else {
                    const size_t idx = (((size_t)bidx * HH + h0) * DHH + dh) * SS + sidx;
                    Ohi[idx] = h_0;
                    Ohi[idx + SS] = h_1;
                    Olo[idx] = l_0;
                    Olo[idx + SS] = l_1;
                }
            }
        }
    }
}

// O projection GEMM (fp32 row-major out)
__global__ __launch_bounds__(256) void o_gemm_kernel(
    const __nv_bfloat16* __restrict__ Ahi, const __nv_bfloat16* __restrict__ Alo,
    const __nv_bfloat16* __restrict__ Whi, const __nv_bfloat16* __restrict__ Wlo,
    const float* __restrict__ bias, float* __restrict__ C)
{
    extern __shared__ char sm[];
    const uint32_t sb = smem_u32(sm);
    const int tid = threadIdx.x;
    const int wid = tid >> 5;
    const int lid = tid & 31;
    const int g = lid >> 2;
    const int t = lid & 3;
    const int bm = blockIdx.y * 128;
    const int bn = blockIdx.x * 128;
    const int wm = (wid & 1) * 64;
    const int wn = (wid >> 1) * 32;

    float acc[4][4][4];
#pragma unroll
    for (int mt = 0; mt < 4; mt++)
#pragma unroll
        for (int nt = 0; nt < 4; nt++)
#pragma unroll
            for (int r = 0; r < 4; r++) acc[mt][nt][r] = 0.0f;

    gemm_mainloop(sm, sb, Ahi, Alo, Whi, Wlo, bm, bn, tid, wm, wn, g, t, acc);

#pragma unroll
    for (int mt = 0; mt < 4; mt++) {
#pragma unroll
        for (int nt = 0; nt < 4; nt++) {
            const float* c = acc[mt][nt];
            const int n0 = bn + wn + nt * 8 + 2 * t;
            const float bia0 = __ldg(&bias[n0]);
            const float bia1 = __ldg(&bias[n0 + 1]);
#pragma unroll
            for (int half = 0; half < 2; half++) {
                const int m = bm + wm + mt * 16 + g + half * 8;
                C[(size_t)m * DD + n0]     = c[half * 2 + 0] + bia0;
                C[(size_t)m * DD + n0 + 1] = c[half * 2 + 1] + bia1;
            }
        }
    }
}

// ---------------------------------------------------------------------------
// Tensor-core flash attention (exact R6 structure, fp32 ctx out)
// ---------------------------------------------------------------------------
#define KSTR 72
#define FTILE_B (64 * KSTR * 2)
#define FSTAGE_B (4 * FTILE_B)
#define FLASH_SMEM (2 * FSTAGE_B)

__global__ __launch_bounds__(128) void flash_tc_kernel(
    const __nv_bfloat16* __restrict__ Qhi, const __nv_bfloat16* __restrict__ Qlo,
    const __nv_bfloat16* __restrict__ Khi, const __nv_bfloat16* __restrict__ Klo,
    const __nv_bfloat16* __restrict__ VThi, const __nv_bfloat16* __restrict__ VTlo,
    float* __restrict__ ctx)
{
    extern __shared__ char sm[];
    const uint32_t sb = smem_u32(sm);
    const int tid = threadIdx.x;
    const int wid = tid >> 5;
    const int lid = tid & 31;
    const int g = lid >> 2;
    const int t = lid & 3;
    const int qb = gridDim.x - 1 - blockIdx.x;
    const int bh = blockIdx.y;

    const size_t hoff = (size_t)bh * SS * DHH;
    const __nv_bfloat16* qhi = Qhi + hoff;
    const __nv_bfloat16* qlo = Qlo + hoff;
    const __nv_bfloat16* khi = Khi + hoff;
    const __nv_bfloat16* klo = Klo + hoff;
    const __nv_bfloat16* vthi = VThi + hoff;
    const __nv_bfloat16* vtlo = VTlo + hoff;

    const int qrow0 = qb * 64 + wid * 16;

    uint32_t qh[4][4], ql[4][4];
#pragma unroll
    for (int s = 0; s < 4; s++) {
        const int cA = s * 16 + 2 * t;
        qh[s][0] = *(const uint32_t*)(qhi + (size_t)(qrow0 + g)     * DHH + cA);
        qh[s][1] = *(const uint32_t*)(qhi + (size_t)(qrow0 + g + 8) * DHH + cA);
        qh[s][2] = *(const uint32_t*)(qhi + (size_t)(qrow0 + g)     * DHH + cA + 8);
        qh[s][3] = *(const uint32_t*)(qhi + (size_t)(qrow0 + g + 8) * DHH + cA + 8);
        ql[s][0] = *(const uint32_t*)(qlo + (size_t)(qrow0 + g)     * DHH + cA);
        ql[s][1] = *(const uint32_t*)(qlo + (size_t)(qrow0 + g + 8) * DHH + cA);
        ql[s][2] = *(const uint32_t*)(qlo + (size_t)(qrow0 + g)     * DHH + cA + 8);
        ql[s][3] = *(const uint32_t*)(qlo + (size_t)(qrow0 + g + 8) * DHH + cA + 8);
    }

    float oa[8][4];
#pragma unroll
    for (int j = 0; j < 8; j++)
#pragma unroll
        for (int r = 0; r < 4; r++) oa[j][r] = 0.0f;
    float mrun0 = -INFINITY, mrun1 = -INFINITY, lrun0 = 0.0f, lrun1 = 0.0f;

    auto load_kv = [&](int jb, int stage) {
        const uint32_t s0 = sb + stage * FSTAGE_B;
        const int kb = jb * 64;
#pragma unroll
        for (int p = 0; p < 4; p++) {
            const int i = p * 128 + tid;
            const int r = i >> 3;
            const int c = i & 7;
            const uint32_t d = r * (KSTR * 2) + c * 16;
            cp16(s0 + 0 * FTILE_B + d, khi  + (size_t)(kb + r) * DHH + c * 8);
            cp16(s0 + 1 * FTILE_B + d, klo  + (size_t)(kb + r) * DHH + c * 8);
            cp16(s0 + 2 * FTILE_B + d, vthi + (size_t)r * SS + kb + c * 8);
            cp16(s0 + 3 * FTILE_B + d, vtlo + (size_t)r * SS + kb + c * 8);
        }
    };

    load_kv(0, 0);
    cp_commit();

    const float scale = 0.125f;

    for (int jb = 0; jb <= qb; jb++) {
        const int s = jb & 1;
        if (jb < qb) {
            load_kv(jb + 1, s ^ 1);
            cp_commit();
            cp_wait<1>();
        } else {
            cp_wait<0>();
        }
        __syncthreads();

        const char* stg = sm + s * FSTAGE_B;
        const char* tKhi = stg + 0 * FTILE_B;
        const char* tKlo = stg + 1 * FTILE_B;
        const char* tVhi = stg + 2 * FTILE_B;
        const char* tVlo = stg + 3 * FTILE_B;

        float sacc[8][4];
#pragma unroll
        for (int j = 0; j < 8; j++)
#pragma unroll
            for (int r = 0; r < 4; r++) sacc[j][r] = 0.0f;

#pragma unroll
        for (int ks = 0; ks < 4; ks++) {
            const int cB = ks * 16 + 2 * t;
            uint32_t kbh[8][2], kbl[8][2];
#pragma unroll
            for (int j = 0; j < 8; j++) {
                const int nr = j * 8 + g;
                kbh[j][0] = *(const uint32_t*)(tKhi + (nr * KSTR + cB)     * 2);
                kbh[j][1] = *(const uint32_t*)(tKhi + (nr * KSTR + cB + 8) * 2);
                kbl[j][0] = *(const uint32_t*)(tKlo + (nr * KSTR + cB)     * 2);
                kbl[j][1] = *(const uint32_t*)(tKlo + (nr * KSTR + cB + 8) * 2);
            }
#pragma unroll
            for (int j = 0; j < 8; j++)
                mma_bf16(sacc[j][0], sacc[j][1], sacc[j][2], sacc[j][3],
                         qh[ks][0], qh[ks][1], qh[ks][2], qh[ks][3],
                         kbh[j][0], kbh[j][1]);
#pragma unroll
            for (int j = 0; j < 8; j++)
                mma_bf16(sacc[j][0], sacc[j][1], sacc[j][2], sacc[j][3],
                         qh[ks][0], qh[ks][1], qh[ks][2], qh[ks][3],
                         kbl[j][0], kbl[j][1]);
#pragma unroll
            for (int j = 0; j < 8; j++)
                mma_bf16(sacc[j][0], sacc[j][1], sacc[j][2], sacc[j][3],
                         ql[ks][0], ql[ks][1], ql[ks][2], ql[ks][3],
                         kbh[j][0], kbh[j][1]);
        }

        const int qg0 = qrow0 + g;
        const int qg1 = qrow0 + g + 8;
        if (jb == qb) {
            const int kbase = jb * 64;
#pragma unroll
            for (int j = 0; j < 8; j++) {
                const int c0 = kbase + j * 8 + 2 * t;
                const int c1 = c0 + 1;
                sacc[j][0] = (c0 > qg0) ? -1e30f : sacc[j][0] * scale;
                sacc[j][1] = (c1 > qg0) ? -1e30f : sacc[j][1] * scale;
                sacc[j][2] = (c0 > qg1) ? -1e30f : sacc[j][2] * scale;
                sacc[j][3] = (c1 > qg1) ? -1e30f : sacc[j][3] * scale;
            }
        } else {
#pragma unroll
            for (int j = 0; j < 8; j++)
#pragma unroll
                for (int r = 0; r < 4; r++) sacc[j][r] *= scale;
        }

        float mt0 = -INFINITY, mt1 = -INFINITY;
#pragma unroll
        for (int j = 0; j < 8; j++) {
            mt0 = fmaxf(mt0, fmaxf(sacc[j][0], sacc[j][1]));
            mt1 = fmaxf(mt1, fmaxf(sacc[j][2], sacc[j][3]));
        }
        mt0 = fmaxf(mt0, __shfl_xor_sync(0xffffffffu, mt0, 1));
        mt0 = fmaxf(mt0, __shfl_xor_sync(0xffffffffu, mt0, 2));
        mt1 = fmaxf(mt1, __shfl_xor_sync(0xffffffffu, mt1, 1));
        mt1 = fmaxf(mt1, __shfl_xor_sync(0xffffffffu, mt1, 2));
        const float mn0 = fmaxf(mrun0, mt0);
        const float mn1 = fmaxf(mrun1, mt1);
        const float al0 = __expf(mrun0 - mn0);
        const float al1 = __expf(mrun1 - mn1);
        float rs0 = 0.0f, rs1 = 0.0f;
#pragma unroll
        for (int j = 0; j < 8; j++) {
            sacc[j][0] = __expf(sacc[j][0] - mn0);
            sacc[j][1] = __expf(sacc[j][1] - mn0);
            sacc[j][2] = __expf(sacc[j][2] - mn1);
            sacc[j][3] = __expf(sacc[j][3] - mn1);
            rs0 += sacc[j][0] + sacc[j][1];
            rs1 += sacc[j][2] + sacc[j][3];
        }
        rs0 += __shfl_xor_sync(0xffffffffu, rs0, 1);
        rs0 += __shfl_xor_sync(0xffffffffu, rs0, 2);
        rs1 += __shfl_xor_sync(0xffffffffu, rs1, 1);
        rs1 += __shfl_xor_sync(0xffffffffu, rs1, 2);
        lrun0 = al0 * lrun0 + rs0;
        lrun1 = al1 * lrun1 + rs1;
        mrun0 = mn0;
        mrun1 = mn1;
#pragma unroll
        for (int j = 0; j < 8; j++) {
            oa[j][0] *= al0;
            oa[j][1] *= al0;
            oa[j][2] *= al1;
            oa[j][3] *= al1;
        }

#pragma unroll
        for (int ks = 0; ks < 4; ks++) {
            const int j0 = 2 * ks, j1 = 2 * ks + 1;
            uint32_t pah[4], pal[4];
            {
                uint32_t h;
                __nv_bfloat162 hb;
                h = pack_bf16x2(sacc[j0][0], sacc[j0][1]);
                hb = *(__nv_bfloat162*)&h;
                pah[0] = h;
                pal[0] = pack_bf16x2(sacc[j0][0] - __bfloat162float(hb.x),
                                     sacc[j0][1] - __bfloat162float(hb.y));
                h = pack_bf16x2(sacc[j0][2], sacc[j0][3]);
                hb = *(__nv_bfloat162*)&h;
                pah[1] = h;
                pal[1] = pack_bf16x2(sacc[j0][2] - __bfloat162float(hb.x),
                                     sacc[j0][3] - __bfloat162float(hb.y));
                h = pack_bf16x2(sacc[j1][0], sacc[j1][1]);
                hb = *(__nv_bfloat162*)&h;
                pah[2] = h;
                pal[2] = pack_bf16x2(sacc[j1][0] - __bfloat162float(hb.x),
                                     sacc[j1][1] - __bfloat162float(hb.y));
                h = pack_bf16x2(sacc[j1][2], sacc[j1][3]);
                hb = *(__nv_bfloat162*)&h;
                pah[3] = h;
                pal[3] = pack_bf16x2(sacc[j1][2] - __bfloat162float(hb.x),
                                     sacc[j1][3] - __bfloat162float(hb.y));
            }
            uint32_t vh[8][2], vl[8][2];
#pragma unroll
            for (int jd = 0; jd < 8; jd++) {
                const int nr = jd * 8 + g;
                const int cB = ks * 16 + 2 * t;
                vh[jd][0] = *(const uint32_t*)(tVhi + (nr * KSTR + cB)     * 2);
                vh[jd][1] = *(const uint32_t*)(tVhi + (nr * KSTR + cB + 8) * 2);
                vl[jd][0] = *(const uint32_t*)(tVlo + (nr * KSTR + cB)     * 2);
                vl[jd][1] = *(const uint32_t*)(tVlo + (nr * KSTR + cB + 8) * 2);
            }
#pragma unroll
            for (int jd = 0; jd < 8; jd++)
                mma_bf16(oa[jd][0], oa[jd][1], oa[jd][2], oa[jd][3],
                         pah[0], pah[1], pah[2], pah[3], vh[jd][0], vh[jd][1]);
#pragma unroll
            for (int jd = 0; jd < 8; jd++)
                mma_bf16(oa[jd][0], oa[jd][1], oa[jd][2], oa[jd][3],
                         pah[0], pah[1], pah[2], pah[3], vl[jd][0], vl[jd][1]);
#pragma unroll
            for (int jd = 0; jd < 8; jd++)
                mma_bf16(oa[jd][0], oa[jd][1], oa[jd][2], oa[jd][3],
                         pal[0], pal[1], pal[2], pal[3], vh[jd][0], vh[jd][1]);
        }
        __syncthreads();
    }

    const int b = bh >> 4;
    const int h = bh & 15;
    const float inv0 = 1.0f / lrun0;
    const float inv1 = 1.0f / lrun1;
#pragma unroll
    for (int jd = 0; jd < 8; jd++) {
        const int dh = jd * 8 + 2 * t;
        float2 r0 = make_float2(oa[jd][0] * inv0, oa[jd][1] * inv0);
        float2 r1 = make_float2(oa[jd][2] * inv1, oa[jd][3] * inv1);
        *(float2*)(ctx + ((size_t)b * SS + qrow0 + g)     * DD + h * DHH + dh) = r0;
        *(float2*)(ctx + ((size_t)b * SS + qrow0 + g + 8) * DD + h * DHH + dh) = r1;
    }
}

// ---------------------------------------------------------------------------
// Launch
// ---------------------------------------------------------------------------
extern "C" void kernel_launch(void* const* d_in, const int* in_sizes, int n_in,
                              void* d_out, int out_size)
{
    const float* query = (const float*)d_in[0];
    const float* key_i = (const float*)d_in[1];
    const float* value = (const float*)d_in[2];
    const float* Wq = (const float*)d_in[4];
    const float* bq = (const float*)d_in[5];
    const float* Wk = (const float*)d_in[6];
    const float* bk = (const float*)d_in[7];
    const float* Wv = (const float*)d_in[8];
    const float* bv = (const float*)d_in[9];
    const float* Wo = (const float*)d_in[10];
    const float* bo = (const float*)d_in[11];
    float* out = (float*)d_out;

    float* ctx;
    __nv_bfloat16 *xhi, *xlo, *whi, *wlo;
    __nv_bfloat16 *qhi, *qlo, *khi, *klo, *vthi, *vtlo;
    cudaGetSymbolAddress((void**)&ctx, g_ctx);
    cudaGetSymbolAddress((void**)&xhi, g_xhi);
    cudaGetSymbolAddress((void**)&xlo, g_xlo);
    cudaGetSymbolAddress((void**)&whi, g_whi);
    cudaGetSymbolAddress((void**)&wlo, g_wlo);
    cudaGetSymbolAddress((void**)&qhi, g_qhi);
    cudaGetSymbolAddress((void**)&qlo, g_qlo);
    cudaGetSymbolAddress((void**)&khi, g_khi);
    cudaGetSymbolAddress((void**)&klo, g_klo);
    cudaGetSymbolAddress((void**)&vthi, g_vthi);
    cudaGetSymbolAddress((void**)&vtlo, g_vtlo);

    const int M = BB * SS;
    const int nX4 = M * DD / 4;
    const int nW4 = DD * DD / 4;

    cudaFuncSetAttribute(qkv_gemm_kernel,
                         cudaFuncAttributeMaxDynamicSharedMemorySize, GEMM_SMEM);
    cudaFuncSetAttribute(o_gemm_kernel,
                         cudaFuncAttributeMaxDynamicSharedMemorySize, GEMM_SMEM);
    cudaFuncSetAttribute(flash_tc_kernel,
                         cudaFuncAttributeMaxDynamicSharedMemorySize, FLASH_SMEM);

    // splits
    split_x3_kernel<<<dim3((nX4 + 255) / 256, 3), 256>>>(
        query, key_i, value, xhi, xlo, nX4);
    split_w4_kernel<<<dim3((nW4 + 255) / 256, 4), 256>>>(
        Wq, Wk, Wv, Wo, whi, wlo, nW4);

    // fused QKV projections (z = 0,1,2)
    qkv_gemm_kernel<<<dim3(DD / 128, M / 128, 3), 256, GEMM_SMEM>>>(
        xhi, xlo, whi, wlo, bq, bk, bv,
        qhi, qlo, khi, klo, vthi, vtlo);

    // tensor-core flash attention
    flash_tc_kernel<<<dim3(SS / 64, BB * HH), 128, FLASH_SMEM>>>(
        qhi, qlo, khi, klo, vthi, vtlo, ctx);

    // O projection
    split_kernel<<<(nX4 + 255) / 256, 256>>>(ctx, xhi, xlo, nX4);
    o_gemm_kernel<<<dim3(DD / 128, M / 128), 256, GEMM_SMEM>>>(
        xhi, xlo, whi + (size_t)3 * DD * DD, wlo + (size_t)3 * DD * DD, bo, out);
}

// round 9
// speedup vs baseline: 1.5432x; 1.0003x over previous
#include <cuda_runtime.h>
#include <cuda_bf16.h>
#include <cuda_fp16.h>
#include <math.h>
#include <stdint.h>

#define BB 4
#define SS 2048
#define DD 1024
#define HH 16
#define DHH 64

// ---------------------------------------------------------------------------
// Scratch (allocation-free __device__ globals)
// ---------------------------------------------------------------------------
__device__ float g_ctx[BB * SS * DD];
__device__ __half g_xhi[3 * BB * SS * DD];          // fp16 hi/lo (GEMM A operands)
__device__ __half g_xlo[3 * BB * SS * DD];
__device__ __half g_whi[4 * DD * DD];
__device__ __half g_wlo[4 * DD * DD];
__device__ __nv_bfloat16 g_qhi[BB * SS * DD];       // [B,H,S,DH]  (flash stays bf16)
__device__ __nv_bfloat16 g_qlo[BB * SS * DD];
__device__ __nv_bfloat16 g_khi[BB * SS * DD];       // [B,H,S,DH]
__device__ __nv_bfloat16 g_klo[BB * SS * DD];
__device__ __nv_bfloat16 g_vthi[BB * SS * DD];      // [B,H,DH,S]
__device__ __nv_bfloat16 g_vtlo[BB * SS * DD];

// ---------------------------------------------------------------------------
// helpers
// ---------------------------------------------------------------------------
__device__ __forceinline__ uint32_t smem_u32(const void* p) {
    uint32_t a;
    asm("{ .reg .u64 t; cvta.to.shared.u64 t, %1; cvt.u32.u64 %0, t; }"
        : "=r"(a) : "l"(p));
    return a;
}
__device__ __forceinline__ void cp16(uint32_t sdst, const void* gsrc) {
    asm volatile("cp.async.cg.shared.global [%0], [%1], 16;"
                 :: "r"(sdst), "l"(gsrc));
}
__device__ __forceinline__ void cp_commit() {
    asm volatile("cp.async.commit_group;");
}
template <int N>
__device__ __forceinline__ void cp_wait() {
    asm volatile("cp.async.wait_group %0;" :: "n"(N));
}
// bf16 inputs, fp32 acc (flash)
__device__ __forceinline__ void mma_bf16(float& c0, float& c1, float& c2, float& c3,
                                         uint32_t a0, uint32_t a1, uint32_t a2, uint32_t a3,
                                         uint32_t b0, uint32_t b1) {
    asm volatile(
        "mma.sync.aligned.m16n8k16.row.col.f32.bf16.bf16.f32 "
        "{%0,%1,%2,%3}, {%4,%5,%6,%7}, {%8,%9}, {%0,%1,%2,%3};"
        : "+f"(c0), "+f"(c1), "+f"(c2), "+f"(c3)
        : "r"(a0), "r"(a1), "r"(a2), "r"(a3), "r"(b0), "r"(b1));
}
// fp16 inputs, fp32 acc (GEMM hi*hi)
__device__ __forceinline__ void mma_f16_f32(float& c0, float& c1, float& c2, float& c3,
                                            uint32_t a0, uint32_t a1, uint32_t a2, uint32_t a3,
                                            uint32_t b0, uint32_t b1) {
    asm volatile(
        "mma.sync.aligned.m16n8k16.row.col.f32.f16.f16.f32 "
        "{%0,%1,%2,%3}, {%4,%5,%6,%7}, {%8,%9}, {%0,%1,%2,%3};"
        : "+f"(c0), "+f"(c1), "+f"(c2), "+f"(c3)
        : "r"(a0), "r"(a1), "r"(a2), "r"(a3), "r"(b0), "r"(b1));
}
// fp16 inputs, fp16 acc (GEMM cross terms) -- 2 packed regs
__device__ __forceinline__ void mma_f16_f16(uint32_t& d0, uint32_t& d1,
                                            uint32_t a0, uint32_t a1, uint32_t a2, uint32_t a3,
                                            uint32_t b0, uint32_t b1) {
    asm volatile(
        "mma.sync.aligned.m16n8k16.row.col.f16.f16.f16.f16 "
        "{%0,%1}, {%2,%3,%4,%5}, {%6,%7}, {%0,%1};"
        : "+r"(d0), "+r"(d1)
        : "r"(a0), "r"(a1), "r"(a2), "r"(a3), "r"(b0), "r"(b1));
}
__device__ __forceinline__ uint32_t pack_bf16x2(float lo, float hi) {
    uint32_t r;
    asm("cvt.rn.bf16x2.f32 %0, %1, %2;" : "=r"(r) : "f"(hi), "f"(lo));
    return r;
}

// ---------------------------------------------------------------------------
// fused fp32 -> fp16 hi/lo splits
// ---------------------------------------------------------------------------
__device__ __forceinline__ void split4(const float* __restrict__ x,
                                       __half* __restrict__ hi,
                                       __half* __restrict__ lo, int i)
{
    float4 v = ((const float4*)x)[i];
    __half h0 = __float2half_rn(v.x);
    __half h1 = __float2half_rn(v.y);
    __half h2 = __float2half_rn(v.z);
    __half h3 = __float2half_rn(v.w);
    __half l0 = __float2half_rn(v.x - __half2float(h0));
    __half l1 = __float2half_rn(v.y - __half2float(h1));
    __half l2 = __float2half_rn(v.z - __half2float(h2));
    __half l3 = __float2half_rn(v.w - __half2float(h3));
    __half2* hp = (__half2*)(hi + (size_t)i * 4);
    __half2* lp = (__half2*)(lo + (size_t)i * 4);
    hp[0] = __half2(h0, h1);
    hp[1] = __half2(h2, h3);
    lp[0] = __half2(l0, l1);
    lp[1] = __half2(l2, l3);
}

__global__ __launch_bounds__(256) void split_x3_kernel(
    const float* __restrict__ x0, const float* __restrict__ x1,
    const float* __restrict__ x2,
    __half* __restrict__ hi, __half* __restrict__ lo, int n4)
{
    const int z = blockIdx.y;
    const float* x = (z == 0) ? x0 : ((z == 1) ? x1 : x2);
    int i = blockIdx.x * blockDim.x + threadIdx.x;
    if (i >= n4) return;
    split4(x, hi + (size_t)z * n4 * 4, lo + (size_t)z * n4 * 4, i);
}

__global__ __launch_bounds__(256) void split_w4_kernel(
    const float* __restrict__ w0, const float* __restrict__ w1,
    const float* __restrict__ w2, const float* __restrict__ w3,
    __half* __restrict__ hi, __half* __restrict__ lo, int n4)
{
    const int z = blockIdx.y;
    const float* w = (z == 0) ? w0 : ((z == 1) ? w1 : ((z == 2) ? w2 : w3));
    int i = blockIdx.x * blockDim.x + threadIdx.x;
    if (i >= n4) return;
    split4(w, hi + (size_t)z * n4 * 4, lo + (size_t)z * n4 * 4, i);
}

__global__ __launch_bounds__(256) void split_kernel(
    const float* __restrict__ x, __half* __restrict__ hi,
    __half* __restrict__ lo, int n4)
{
    int i = blockIdx.x * blockDim.x + threadIdx.x;
    if (i >= n4) return;
    split4(x, hi, lo, i);
}

// ---------------------------------------------------------------------------
// GEMM: CTA 128x128, 256 thr (8 warps, 2M x 4N), BK=64, 3-stage cp.async.
// hi*hi -> fp32-acc MMA; cross terms -> fp16-acc MMA (packed), added in epilogue.
// ---------------------------------------------------------------------------
#define BK 64
#define NKC (DD / BK)
#define TSTRIDE 72
#define TILE_B (128 * TSTRIDE * 2)
#define STAGE_B (4 * TILE_B)
#define NSTAGE 3
#define GEMM_SMEM (NSTAGE * STAGE_B)  // 221184

__device__ __forceinline__ void load_tile_async(
    uint32_t sbase, const __half* __restrict__ src,
    int row_base, int k0, int tid)
{
#pragma unroll
    for (int p = 0; p < 4; p++) {
        const int i = p * 256 + tid;
        const int r = i >> 3;
        const int c = i & 7;
        cp16(sbase + r * (TSTRIDE * 2) + c * 16,
             src + (size_t)(row_base + r) * DD + k0 + c * 8);
    }
}

__device__ __forceinline__ void load_stage(
    uint32_t sbase, const __half* Ahi, const __half* Alo,
    const __half* Whi, const __half* Wlo,
    int bm, int bn, int k0, int tid)
{
    load_tile_async(sbase + 0 * TILE_B, Ahi, bm, k0, tid);
    load_tile_async(sbase + 1 * TILE_B, Alo, bm, k0, tid);
    load_tile_async(sbase + 2 * TILE_B, Whi, bn, k0, tid);
    load_tile_async(sbase + 3 * TILE_B, Wlo, bn, k0, tid);
    cp_commit();
}

__device__ __forceinline__ void gemm_mainloop(
    char* sm, uint32_t sb,
    const __half* Ahi, const __half* Alo,
    const __half* Whi, const __half* Wlo,
    int bm, int bn, int tid, int wm, int wn, int g, int t,
    float acc[4][4][4], uint32_t xacc[4][4][2])
{
    load_stage(sb + 0 * STAGE_B, Ahi, Alo, Whi, Wlo, bm, bn, 0, tid);
    load_stage(sb + 1 * STAGE_B, Ahi, Alo, Whi, Wlo, bm, bn, BK, tid);

    for (int kc = 0; kc < NKC; kc++) {
        if (kc + 2 < NKC) {
            load_stage(sb + ((kc + 2) % NSTAGE) * STAGE_B,
                       Ahi, Alo, Whi, Wlo, bm, bn, (kc + 2) * BK, tid);
            cp_wait<2>();
        } else if (kc + 1 < NKC) {
            cp_wait<1>();
        } else {
            cp_wait<0>();
        }
        __syncthreads();

        const char* stg = sm + (kc % NSTAGE) * STAGE_B;
        const char* tAhi = stg + 0 * TILE_B;
        const char* tAlo = stg + 1 * TILE_B;
        const char* tWhi = stg + 2 * TILE_B;
        const char* tWlo = stg + 3 * TILE_B;

#pragma unroll
        for (int k16 = 0; k16 < 4; k16++) {
            const int k0 = k16 * 16;
            uint32_t ah[4][4], al[4][4], bh[4][2], bl[4][2];
#pragma unroll
            for (int mt = 0; mt < 4; mt++) {
                const int r0 = wm + mt * 16 + g;
                const int cA = k0 + 2 * t;
                ah[mt][0] = *(const uint32_t*)(tAhi + ((r0)     * TSTRIDE + cA)     * 2);
                ah[mt][1] = *(const uint32_t*)(tAhi + ((r0 + 8) * TSTRIDE + cA)     * 2);
                ah[mt][2] = *(const uint32_t*)(tAhi + ((r0)     * TSTRIDE + cA + 8) * 2);
                ah[mt][3] = *(const uint32_t*)(tAhi + ((r0 + 8) * TSTRIDE + cA + 8) * 2);
                al[mt][0] = *(const uint32_t*)(tAlo + ((r0)     * TSTRIDE + cA)     * 2);
                al[mt][1] = *(const uint32_t*)(tAlo + ((r0 + 8) * TSTRIDE + cA)     * 2);
                al[mt][2] = *(const uint32_t*)(tAlo + ((r0)     * TSTRIDE + cA + 8) * 2);
                al[mt][3] = *(const uint32_t*)(tAlo + ((r0 + 8) * TSTRIDE + cA + 8) * 2);
            }
#pragma unroll
            for (int nt = 0; nt < 4; nt++) {
                const int nr = wn + nt * 8 + g;
                const int cB = k0 + 2 * t;
                bh[nt][0] = *(const uint32_t*)(tWhi + (nr * TSTRIDE + cB)     * 2);
                bh[nt][1] = *(const uint32_t*)(tWhi + (nr * TSTRIDE + cB + 8) * 2);
                bl[nt][0] = *(const uint32_t*)(tWlo + (nr * TSTRIDE + cB)     * 2);
                bl[nt][1] = *(const uint32_t*)(tWlo + (nr * TSTRIDE + cB + 8) * 2);
            }
#pragma unroll
            for (int mt = 0; mt < 4; mt++)
#pragma unroll
                for (int nt = 0; nt < 4; nt++) {
                    float* c = acc[mt][nt];
                    uint32_t* x = xacc[mt][nt];
                    mma_f16_f32(c[0], c[1], c[2], c[3],
                                ah[mt][0], ah[mt][1], ah[mt][2], ah[mt][3],
                                bh[nt][0], bh[nt][1]);
                    mma_f16_f16(x[0], x[1],
                                ah[mt][0], ah[mt][1], ah[mt][2], ah[mt][3],
                                bl[nt][0], bl[nt][1]);
                    mma_f16_f16(x[0], x[1],
                                al[mt][0], al[mt][1], al[mt][2], al[mt][3],
                                bh[nt][0], bh[nt][1]);
                }
        }
        __syncthreads();
    }
}

// merge fp16 cross accumulator into fp32 acc (c0,c1 <- x0; c2,c3 <- x1)
__device__ __forceinline__ void merge_cross(float* c, const uint32_t* x) {
    __half2 h0 = *(const __half2*)&x[0];
    __half2 h1 = *(const __half2*)&x[1];
    c[0] += __half2float(h0.x);
    c[1] += __half2float(h0.y);
    c[2] += __half2float(h1.x);
    c[3] += __half2float(h1.y);
}

// fused QKV projection GEMM: gridDim.z selects {Q, K, V}
__global__ __launch_bounds__(256) void qkv_gemm_kernel(
    const __half* __restrict__ xhi, const __half* __restrict__ xlo,
    const __half* __restrict__ whi, const __half* __restrict__ wlo,
    const float* __restrict__ bq, const float* __restrict__ bk,
    const float* __restrict__ bv,
    __nv_bfloat16* __restrict__ qhi, __nv_bfloat16* __restrict__ qlo,
    __nv_bfloat16* __restrict__ khi, __nv_bfloat16* __restrict__ klo,
    __nv_bfloat16* __restrict__ vthi, __nv_bfloat16* __restrict__ vtlo)
{
    extern __shared__ char sm[];
    const uint32_t sb = smem_u32(sm);
    const int tid = threadIdx.x;
    const int wid = tid >> 5;
    const int lid = tid & 31;
    const int g = lid >> 2;
    const int t = lid & 3;
    const int bm = blockIdx.y * 128;
    const int bn = blockIdx.x * 128;
    const int wm = (wid & 1) * 64;
    const int wn = (wid >> 1) * 32;
    const int z = blockIdx.z;

    const size_t Msz = (size_t)BB * SS * DD;
    const __half* Ahi = xhi + (size_t)z * Msz;
    const __half* Alo = xlo + (size_t)z * Msz;
    const __half* Whi = whi + (size_t)z * DD * DD;
    const __half* Wlo = wlo + (size_t)z * DD * DD;
    const float* bias = (z == 0) ? bq : ((z == 1) ? bk : bv);
    __nv_bfloat16* Ohi = (z == 0) ? qhi : ((z == 1) ? khi : vthi);
    __nv_bfloat16* Olo = (z == 0) ? qlo : ((z == 1) ? klo : vtlo);

    float acc[4][4][4];
    uint32_t xacc[4][4][2];
#pragma unroll
    for (int mt = 0; mt < 4; mt++)
#pragma unroll
        for (int nt = 0; nt < 4; nt++) {
#pragma unroll
            for (int r = 0; r < 4; r++) acc[mt][nt][r] = 0.0f;
            xacc[mt][nt][0] = 0u;
            xacc[mt][nt][1] = 0u;
        }

    gemm_mainloop(sm, sb, Ahi, Alo, Whi, Wlo, bm, bn, tid, wm, wn, g, t,
                  acc, xacc);

    const bool trans = (z == 2);
#pragma unroll
    for (int mt = 0; mt < 4; mt++) {
#pragma unroll
        for (int nt = 0; nt < 4; nt++) {
            float* c = acc[mt][nt];
            merge_cross(c, xacc[mt][nt]);
            const int n0 = bn + wn + nt * 8 + 2 * t;
            const float bia0 = __ldg(&bias[n0]);
            const float bia1 = __ldg(&bias[n0 + 1]);
#pragma unroll
            for (int half = 0; half < 2; half++) {
                const int m = bm + wm + mt * 16 + g + half * 8;
                const float v0 = c[half * 2 + 0] + bia0;
                const float v1 = c[half * 2 + 1] + bia1;
                const int bidx = m >> 11;
                const int sidx = m & (SS - 1);
                const int h0 = n0 >> 6;
                const int dh = n0 & (DHH - 1);
                __nv_bfloat16 h_0 = __float2bfloat16_rn(v0);
                __nv_bfloat16 h_1 = __float2bfloat16_rn(v1);
                __nv_bfloat16 l_0 = __float2bfloat16_rn(v0 - __bfloat162float(h_0));
                __nv_bfloat16 l_1 = __float2bfloat16_rn(v1 - __bfloat162float(h_1));
                if (!trans) {
                    const size_t idx = (((size_t)bidx * HH + h0) * SS + sidx) * DHH + dh;
                    *(__nv_bfloat162*)(Ohi + idx) = __nv_bfloat162(h_0, h_1);
                    *(__nv_bfloat162*)(Olo + idx) = __nv_bfloat162(l_0, l_1);
                } else {
                    const size_t idx = (((size_t)bidx * HH + h0) * DHH + dh) * SS + sidx;
                    Ohi[idx] = h_0;
                    Ohi[idx + SS] = h_1;
                    Olo[idx] = l_0;
                    Olo[idx + SS] = l_1;
                }
            }
        }
    }
}

// O projection GEMM (fp32 row-major out)
__global__ __launch_bounds__(256) void o_gemm_kernel(
    const __half* __restrict__ Ahi, const __half* __restrict__ Alo,
    const __half* __restrict__ Whi, const __half* __restrict__ Wlo,
    const float* __restrict__ bias, float* __restrict__ C)
{
    extern __shared__ char sm[];
    const uint32_t sb = smem_u32(sm);
    const int tid = threadIdx.x;
    const int wid = tid >> 5;
    const int lid = tid & 31;
    const int g = lid >> 2;
    const int t = lid & 3;
    const int bm = blockIdx.y * 128;
    const int bn = blockIdx.x * 128;
    const int wm = (wid & 1) * 64;
    const int wn = (wid >> 1) * 32;

    float acc[4][4][4];
    uint32_t xacc[4][4][2];
#pragma unroll
    for (int mt = 0; mt < 4; mt++)
#pragma unroll
        for (int nt = 0; nt < 4; nt++) {
#pragma unroll
            for (int r = 0; r < 4; r++) acc[mt][nt][r] = 0.0f;
            xacc[mt][nt][0] = 0u;
            xacc[mt][nt][1] = 0u;
        }

    gemm_mainloop(sm, sb, Ahi, Alo, Whi, Wlo, bm, bn, tid, wm, wn, g, t,
                  acc, xacc);

#pragma unroll
    for (int mt = 0; mt < 4; mt++) {
#pragma unroll
        for (int nt = 0; nt < 4; nt++) {
            float* c = acc[mt][nt];
            merge_cross(c, xacc[mt][nt]);
            const int n0 = bn + wn + nt * 8 + 2 * t;
            const float bia0 = __ldg(&bias[n0]);
            const float bia1 = __ldg(&bias[n0 + 1]);
#pragma unroll
            for (int half = 0; half < 2; half++) {
                const int m = bm + wm + mt * 16 + g + half * 8;
                C[(size_t)m * DD + n0]     = c[half * 2 + 0] + bia0;
                C[(size_t)m * DD + n0 + 1] = c[half * 2 + 1] + bia1;
            }
        }
    }
}

// ---------------------------------------------------------------------------
// Tensor-core flash attention (exact R8 structure, bf16, fp32 ctx out)
// ---------------------------------------------------------------------------
#define KSTR 72
#define FTILE_B (64 * KSTR * 2)
#define FSTAGE_B (4 * FTILE_B)
#define FLASH_SMEM (2 * FSTAGE_B)

__global__ __launch_bounds__(128) void flash_tc_kernel(
    const __nv_bfloat16* __restrict__ Qhi, const __nv_bfloat16* __restrict__ Qlo,
    const __nv_bfloat16* __restrict__ Khi, const __nv_bfloat16* __restrict__ Klo,
    const __nv_bfloat16* __restrict__ VThi, const __nv_bfloat16* __restrict__ VTlo,
    float* __restrict__ ctx)
{
    extern __shared__ char sm[];
    const uint32_t sb = smem_u32(sm);
    const int tid = threadIdx.x;
    const int wid = tid >> 5;
    const int lid = tid & 31;
    const int g = lid >> 2;
    const int t = lid & 3;
    const int qb = gridDim.x - 1 - blockIdx.x;
    const int bh = blockIdx.y;

    const size_t hoff = (size_t)bh * SS * DHH;
    const __nv_bfloat16* qhi = Qhi + hoff;
    const __nv_bfloat16* qlo = Qlo + hoff;
    const __nv_bfloat16* khi = Khi + hoff;
    const __nv_bfloat16* klo = Klo + hoff;
    const __nv_bfloat16* vthi = VThi + hoff;
    const __nv_bfloat16* vtlo = VTlo + hoff;

    const int qrow0 = qb * 64 + wid * 16;

    uint32_t qh[4][4], ql[4][4];
#pragma unroll
    for (int s = 0; s < 4; s++) {
        const int cA = s * 16 + 2 * t;
        qh[s][0] = *(const uint32_t*)(qhi + (size_t)(qrow0 + g)     * DHH + cA);
        qh[s][1] = *(const uint32_t*)(qhi + (size_t)(qrow0 + g + 8) * DHH + cA);
        qh[s][2] = *(const uint32_t*)(qhi + (size_t)(qrow0 + g)     * DHH + cA + 8);
        qh[s][3] = *(const uint32_t*)(qhi + (size_t)(qrow0 + g + 8) * DHH + cA + 8);
        ql[s][0] = *(const uint32_t*)(qlo + (size_t)(qrow0 + g)     * DHH + cA);
        ql[s][1] = *(const uint32_t*)(qlo + (size_t)(qrow0 + g + 8) * DHH + cA);
        ql[s][2] = *(const uint32_t*)(qlo + (size_t)(qrow0 + g)     * DHH + cA + 8);
        ql[s][3] = *(const uint32_t*)(qlo + (size_t)(qrow0 + g + 8) * DHH + cA + 8);
    }

    float oa[8][4];
#pragma unroll
    for (int j = 0; j < 8; j++)
#pragma unroll
        for (int r = 0; r < 4; r++) oa[j][r] = 0.0f;
    float mrun0 = -INFINITY, mrun1 = -INFINITY, lrun0 = 0.0f, lrun1 = 0.0f;

    auto load_kv = [&](int jb, int stage) {
        const uint32_t s0 = sb + stage * FSTAGE_B;
        const int kb = jb * 64;
#pragma unroll
        for (int p = 0; p < 4; p++) {
            const int i = p * 128 + tid;
            const int r = i >> 3;
            const int c = i & 7;
            const uint32_t d = r * (KSTR * 2) + c * 16;
            cp16(s0 + 0 * FTILE_B + d, khi  + (size_t)(kb + r) * DHH + c * 8);
            cp16(s0 + 1 * FTILE_B + d, klo  + (size_t)(kb + r) * DHH + c * 8);
            cp16(s0 + 2 * FTILE_B + d, vthi + (size_t)r * SS + kb + c * 8);
            cp16(s0 + 3 * FTILE_B + d, vtlo + (size_t)r * SS + kb + c * 8);
        }
    };

    load_kv(0, 0);
    cp_commit();

    const float scale = 0.125f;

    for (int jb = 0; jb <= qb; jb++) {
        const int s = jb & 1;
        if (jb < qb) {
            load_kv(jb + 1, s ^ 1);
            cp_commit();
            cp_wait<1>();
        } else {
            cp_wait<0>();
        }
        __syncthreads();

        const char* stg = sm + s * FSTAGE_B;
        const char* tKhi = stg + 0 * FTILE_B;
        const char* tKlo = stg + 1 * FTILE_B;
        const char* tVhi = stg + 2 * FTILE_B;
        const char* tVlo = stg + 3 * FTILE_B;

        float sacc[8][4];
#pragma unroll
        for (int j = 0; j < 8; j++)
#pragma unroll
            for (int r = 0; r < 4; r++) sacc[j][r] = 0.0f;

#pragma unroll
        for (int ks = 0; ks < 4; ks++) {
            const int cB = ks * 16 + 2 * t;
            uint32_t kbh[8][2], kbl[8][2];
#pragma unroll
            for (int j = 0; j < 8; j++) {
                const int nr = j * 8 + g;
                kbh[j][0] = *(const uint32_t*)(tKhi + (nr * KSTR + cB)     * 2);
                kbh[j][1] = *(const uint32_t*)(tKhi + (nr * KSTR + cB + 8) * 2);
                kbl[j][0] = *(const uint32_t*)(tKlo + (nr * KSTR + cB)     * 2);
                kbl[j][1] = *(const uint32_t*)(tKlo + (nr * KSTR + cB + 8) * 2);
            }
#pragma unroll
            for (int j = 0; j < 8; j++)
                mma_bf16(sacc[j][0], sacc[j][1], sacc[j][2], sacc[j][3],
                         qh[ks][0], qh[ks][1], qh[ks][2], qh[ks][3],
                         kbh[j][0], kbh[j][1]);
#pragma unroll
            for (int j = 0; j < 8; j++)
                mma_bf16(sacc[j][0], sacc[j][1], sacc[j][2], sacc[j][3],
                         qh[ks][0], qh[ks][1], qh[ks][2], qh[ks][3],
                         kbl[j][0], kbl[j][1]);
#pragma unroll
            for (int j = 0; j < 8; j++)
                mma_bf16(sacc[j][0], sacc[j][1], sacc[j][2], sacc[j][3],
                         ql[ks][0], ql[ks][1], ql[ks][2], ql[ks][3],
                         kbh[j][0], kbh[j][1]);
        }

        const int qg0 = qrow0 + g;
        const int qg1 = qrow0 + g + 8;
        if (jb == qb) {
            const int kbase = jb * 64;
#pragma unroll
            for (int j = 0; j < 8; j++) {
                const int c0 = kbase + j * 8 + 2 * t;
                const int c1 = c0 + 1;
                sacc[j][0] = (c0 > qg0) ? -1e30f : sacc[j][0] * scale;
                sacc[j][1] = (c1 > qg0) ? -1e30f : sacc[j][1] * scale;
                sacc[j][2] = (c0 > qg1) ? -1e30f : sacc[j][2] * scale;
                sacc[j][3] = (c1 > qg1) ? -1e30f : sacc[j][3] * scale;
            }
        } else {
#pragma unroll
            for (int j = 0; j < 8; j++)
#pragma unroll
                for (int r = 0; r < 4; r++) sacc[j][r] *= scale;
        }

        float mt0 = -INFINITY, mt1 = -INFINITY;
#pragma unroll
        for (int j = 0; j < 8; j++) {
            mt0 = fmaxf(mt0, fmaxf(sacc[j][0], sacc[j][1]));
            mt1 = fmaxf(mt1, fmaxf(sacc[j][2], sacc[j][3]));
        }
        mt0 = fmaxf(mt0, __shfl_xor_sync(0xffffffffu, mt0, 1));
        mt0 = fmaxf(mt0, __shfl_xor_sync(0xffffffffu, mt0, 2));
        mt1 = fmaxf(mt1, __shfl_xor_sync(0xffffffffu, mt1, 1));
        mt1 = fmaxf(mt1, __shfl_xor_sync(0xffffffffu, mt1, 2));
        const float mn0 = fmaxf(mrun0, mt0);
        const float mn1 = fmaxf(mrun1, mt1);
        const float al0 = __expf(mrun0 - mn0);
        const float al1 = __expf(mrun1 - mn1);
        float rs0 = 0.0f, rs1 = 0.0f;
#pragma unroll
        for (int j = 0; j < 8; j++) {
            sacc[j][0] = __expf(sacc[j][0] - mn0);
            sacc[j][1] = __expf(sacc[j][1] - mn0);
            sacc[j][2] = __expf(sacc[j][2] - mn1);
            sacc[j][3] = __expf(sacc[j][3] - mn1);
            rs0 += sacc[j][0] + sacc[j][1];
            rs1 += sacc[j][2] + sacc[j][3];
        }
        rs0 += __shfl_xor_sync(0xffffffffu, rs0, 1);
        rs0 += __shfl_xor_sync(0xffffffffu, rs0, 2);
        rs1 += __shfl_xor_sync(0xffffffffu, rs1, 1);
        rs1 += __shfl_xor_sync(0xffffffffu, rs1, 2);
        lrun0 = al0 * lrun0 + rs0;
        lrun1 = al1 * lrun1 + rs1;
        mrun0 = mn0;
        mrun1 = mn1;
#pragma unroll
        for (int j = 0; j < 8; j++) {
            oa[j][0] *= al0;
            oa[j][1] *= al0;
            oa[j][2] *= al1;
            oa[j][3] *= al1;
        }

#pragma unroll
        for (int ks = 0; ks < 4; ks++) {
            const int j0 = 2 * ks, j1 = 2 * ks + 1;
            uint32_t pah[4], pal[4];
            {
                uint32_t h;
                __nv_bfloat162 hb;
                h = pack_bf16x2(sacc[j0][0], sacc[j0][1]);
                hb = *(__nv_bfloat162*)&h;
                pah[0] = h;
                pal[0] = pack_bf16x2(sacc[j0][0] - __bfloat162float(hb.x),
                                     sacc[j0][1] - __bfloat162float(hb.y));
                h = pack_bf16x2(sacc[j0][2], sacc[j0][3]);
                hb = *(__nv_bfloat162*)&h;
                pah[1] = h;
                pal[1] = pack_bf16x2(sacc[j0][2] - __bfloat162float(hb.x),
                                     sacc[j0][3] - __bfloat162float(hb.y));
                h = pack_bf16x2(sacc[j1][0], sacc[j1][1]);
                hb = *(__nv_bfloat162*)&h;
                pah[2] = h;
                pal[2] = pack_bf16x2(sacc[j1][0] - __bfloat162float(hb.x),
                                     sacc[j1][1] - __bfloat162float(hb.y));
                h = pack_bf16x2(sacc[j1][2], sacc[j1][3]);
                hb = *(__nv_bfloat162*)&h;
                pah[3] = h;
                pal[3] = pack_bf16x2(sacc[j1][2] - __bfloat162float(hb.x),
                                     sacc[j1][3] - __bfloat162float(hb.y));
            }
            uint32_t vh[8][2], vl[8][2];
#pragma unroll
            for (int jd = 0; jd < 8; jd++) {
                const int nr = jd * 8 + g;
                const int cB = ks * 16 + 2 * t;
                vh[jd][0] = *(const uint32_t*)(tVhi + (nr * KSTR + cB)     * 2);
                vh[jd][1] = *(const uint32_t*)(tVhi + (nr * KSTR + cB + 8) * 2);
                vl[jd][0] = *(const uint32_t*)(tVlo + (nr * KSTR + cB)     * 2);
                vl[jd][1] = *(const uint32_t*)(tVlo + (nr * KSTR + cB + 8) * 2);
            }
#pragma unroll
            for (int jd = 0; jd < 8; jd++)
                mma_bf16(oa[jd][0], oa[jd][1], oa[jd][2], oa[jd][3],
                         pah[0], pah[1], pah[2], pah[3], vh[jd][0], vh[jd][1]);
#pragma unroll
            for (int jd = 0; jd < 8; jd++)
                mma_bf16(oa[jd][0], oa[jd][1], oa[jd][2], oa[jd][3],
                         pah[0], pah[1], pah[2], pah[3], vl[jd][0], vl[jd][1]);
#pragma unroll
            for (int jd = 0; jd < 8; jd++)
                mma_bf16(oa[jd][0], oa[jd][1], oa[jd][2], oa[jd][3],
                         pal[0], pal[1], pal[2], pal[3], vh[jd][0], vh[jd][1]);
        }
        __syncthreads();
    }

    const int b = bh >> 4;
    const int h = bh & 15;
    const float inv0 = 1.0f / lrun0;
    const float inv1 = 1.0f / lrun1;
#pragma unroll
    for (int jd = 0; jd < 8; jd++) {
        const int dh = jd * 8 + 2 * t;
        float2 r0 = make_float2(oa[jd][0] * inv0, oa[jd][1] * inv0);
        float2 r1 = make_float2(oa[jd][2] * inv1, oa[jd][3] * inv1);
        *(float2*)(ctx + ((size_t)b * SS + qrow0 + g)     * DD + h * DHH + dh) = r0;
        *(float2*)(ctx + ((size_t)b * SS + qrow0 + g + 8) * DD + h * DHH + dh) = r1;
    }
}

// ---------------------------------------------------------------------------
// Launch
// ---------------------------------------------------------------------------
extern "C" void kernel_launch(void* const* d_in, const int* in_sizes, int n_in,
                              void* d_out, int out_size)
{
    const float* query = (const float*)d_in[0];
    const float* key_i = (const float*)d_in[1];
    const float* value = (const float*)d_in[2];
    const float* Wq = (const float*)d_in[4];
    const float* bq = (const float*)d_in[5];
    const float* Wk = (const float*)d_in[6];
    const float* bk = (const float*)d_in[7];
    const float* Wv = (const float*)d_in[8];
    const float* bv = (const float*)d_in[9];
    const float* Wo = (const float*)d_in[10];
    const float* bo = (const float*)d_in[11];
    float* out = (float*)d_out;

    float* ctx;
    __half *xhi, *xlo, *whi, *wlo;
    __nv_bfloat16 *qhi, *qlo, *khi, *klo, *vthi, *vtlo;
    cudaGetSymbolAddress((void**)&ctx, g_ctx);
    cudaGetSymbolAddress((void**)&xhi, g_xhi);
    cudaGetSymbolAddress((void**)&xlo, g_xlo);
    cudaGetSymbolAddress((void**)&whi, g_whi);
    cudaGetSymbolAddress((void**)&wlo, g_wlo);
    cudaGetSymbolAddress((void**)&qhi, g_qhi);
    cudaGetSymbolAddress((void**)&qlo, g_qlo);
    cudaGetSymbolAddress((void**)&khi, g_khi);
    cudaGetSymbolAddress((void**)&klo, g_klo);
    cudaGetSymbolAddress((void**)&vthi, g_vthi);
    cudaGetSymbolAddress((void**)&vtlo, g_vtlo);

    const int M = BB * SS;
    const int nX4 = M * DD / 4;
    const int nW4 = DD * DD / 4;

    cudaFuncSetAttribute(qkv_gemm_kernel,
                         cudaFuncAttributeMaxDynamicSharedMemorySize, GEMM_SMEM);
    cudaFuncSetAttribute(o_gemm_kernel,
                         cudaFuncAttributeMaxDynamicSharedMemorySize, GEMM_SMEM);
    cudaFuncSetAttribute(flash_tc_kernel,
                         cudaFuncAttributeMaxDynamicSharedMemorySize, FLASH_SMEM);

    // splits (fp16 hi/lo)
    split_x3_kernel<<<dim3((nX4 + 255) / 256, 3), 256>>>(
        query, key_i, value, xhi, xlo, nX4);
    split_w4_kernel<<<dim3((nW4 + 255) / 256, 4), 256>>>(
        Wq, Wk, Wv, Wo, whi, wlo, nW4);

    // fused QKV projections (z = 0,1,2)
    qkv_gemm_kernel<<<dim3(DD / 128, M / 128, 3), 256, GEMM_SMEM>>>(
        xhi, xlo, whi, wlo, bq, bk, bv,
        qhi, qlo, khi, klo, vthi, vtlo);

    // tensor-core flash attention (bf16, unchanged)
    flash_tc_kernel<<<dim3(SS / 64, BB * HH), 128, FLASH_SMEM>>>(
        qhi, qlo, khi, klo, vthi, vtlo, ctx);

    // O projection
    split_kernel<<<(nX4 + 255) / 256, 256>>>(ctx, xhi, xlo, nX4);
    o_gemm_kernel<<<dim3(DD / 128, M / 128), 256, GEMM_SMEM>>>(
        xhi, xlo, whi + (size_t)3 * DD * DD, wlo + (size_t)3 * DD * DD, bo, out);
}

// round 10
// speedup vs baseline: 2.0963x; 1.3584x over previous
#include <cuda_runtime.h>
#include <cuda_fp16.h>
#include <math.h>
#include <stdint.h>

#define BB 4
#define SS 2048
#define DD 1024
#define HH 16
#define DHH 64

// ---------------------------------------------------------------------------
// Scratch (allocation-free __device__ globals)
// ---------------------------------------------------------------------------
__device__ __half g_xhi[3 * BB * SS * DD];   // q/k/v GEMM A (hi only); slot0 reused for ctx
__device__ __half g_whi[4 * DD * DD];        // Wq,Wk,Wv,Wo hi
__device__ __half g_wlo[4 * DD * DD];        // lo
__device__ __half g_qhi[BB * SS * DD];       // [B,H,S,DH] (hi only needed)
__device__ __half g_qlo[BB * SS * DD];
__device__ __half g_khi[BB * SS * DD];       // [B,H,S,DH]
__device__ __half g_klo[BB * SS * DD];
__device__ __half g_vthi[BB * SS * DD];      // [B,H,DH,S]
__device__ __half g_vtlo[BB * SS * DD];

// ---------------------------------------------------------------------------
// helpers
// ---------------------------------------------------------------------------
__device__ __forceinline__ uint32_t smem_u32(const void* p) {
    uint32_t a;
    asm("{ .reg .u64 t; cvta.to.shared.u64 t, %1; cvt.u32.u64 %0, t; }"
        : "=r"(a) : "l"(p));
    return a;
}
__device__ __forceinline__ void cp16(uint32_t sdst, const void* gsrc) {
    asm volatile("cp.async.cg.shared.global [%0], [%1], 16;"
                 :: "r"(sdst), "l"(gsrc));
}
__device__ __forceinline__ void cp_commit() {
    asm volatile("cp.async.commit_group;");
}
template <int N>
__device__ __forceinline__ void cp_wait() {
    asm volatile("cp.async.wait_group %0;" :: "n"(N));
}
// fp16 inputs, fp32 acc
__device__ __forceinline__ void mma_f16(float& c0, float& c1, float& c2, float& c3,
                                        uint32_t a0, uint32_t a1, uint32_t a2, uint32_t a3,
                                        uint32_t b0, uint32_t b1) {
    asm volatile(
        "mma.sync.aligned.m16n8k16.row.col.f32.f16.f16.f32 "
        "{%0,%1,%2,%3}, {%4,%5,%6,%7}, {%8,%9}, {%0,%1,%2,%3};"
        : "+f"(c0), "+f"(c1), "+f"(c2), "+f"(c3)
        : "r"(a0), "r"(a1), "r"(a2), "r"(a3), "r"(b0), "r"(b1));
}
__device__ __forceinline__ uint32_t pack_f16x2(float a, float b) {
    __half2 h = __floats2half2_rn(a, b);   // low = a, high = b
    return *(uint32_t*)&h;
}

// ---------------------------------------------------------------------------
// splits
// ---------------------------------------------------------------------------
// inputs q/k/v -> fp16 hi only
__global__ __launch_bounds__(256) void split_x3_kernel(
    const float* __restrict__ x0, const float* __restrict__ x1,
    const float* __restrict__ x2, __half* __restrict__ hi, int n4)
{
    const int z = blockIdx.y;
    const float* x = (z == 0) ? x0 : ((z == 1) ? x1 : x2);
    int i = blockIdx.x * blockDim.x + threadIdx.x;
    if (i >= n4) return;
    float4 v = ((const float4*)x)[i];
    __half2* hp = (__half2*)(hi + (size_t)z * n4 * 4 + (size_t)i * 4);
    hp[0] = __floats2half2_rn(v.x, v.y);
    hp[1] = __floats2half2_rn(v.z, v.w);
}

// weights -> fp16 hi/lo
__global__ __launch_bounds__(256) void split_w4_kernel(
    const float* __restrict__ w0, const float* __restrict__ w1,
    const float* __restrict__ w2, const float* __restrict__ w3,
    __half* __restrict__ hi, __half* __restrict__ lo, int n4)
{
    const int z = blockIdx.y;
    const float* w = (z == 0) ? w0 : ((z == 1) ? w1 : ((z == 2) ? w2 : w3));
    int i = blockIdx.x * blockDim.x + threadIdx.x;
    if (i >= n4) return;
    float4 v = ((const float4*)w)[i];
    __half h0 = __float2half_rn(v.x);
    __half h1 = __float2half_rn(v.y);
    __half h2 = __float2half_rn(v.z);
    __half h3 = __float2half_rn(v.w);
    __half l0 = __float2half_rn(v.x - __half2float(h0));
    __half l1 = __float2half_rn(v.y - __half2float(h1));
    __half l2 = __float2half_rn(v.z - __half2float(h2));
    __half l3 = __float2half_rn(v.w - __half2float(h3));
    __half2* hp = (__half2*)(hi + (size_t)z * n4 * 4 + (size_t)i * 4);
    __half2* lp = (__half2*)(lo + (size_t)z * n4 * 4 + (size_t)i * 4);
    hp[0] = __halves2half2(h0, h1);
    hp[1] = __halves2half2(h2, h3);
    lp[0] = __halves2half2(l0, l1);
    lp[1] = __halves2half2(l2, l3);
}

// ---------------------------------------------------------------------------
// GEMM: CTA 128x128, 256 thr (8 warps, 2M x 4N), BK=64, 3-stage cp.async.
// 2-term: C = Ah*(Wh + Wl) in fp32 acc. Stage = {Ah, Wh, Wl} tiles.
// ---------------------------------------------------------------------------
#define BK 64
#define NKC (DD / BK)
#define TSTRIDE 72
#define TILE_B (128 * TSTRIDE * 2)   // 18432
#define STAGE_B (3 * TILE_B)         // 55296
#define NSTAGE 3
#define GEMM_SMEM (NSTAGE * STAGE_B) // 165888

__device__ __forceinline__ void load_tile_async(
    uint32_t sbase, const __half* __restrict__ src,
    int row_base, int k0, int tid)
{
#pragma unroll
    for (int p = 0; p < 4; p++) {
        const int i = p * 256 + tid;
        const int r = i >> 3;
        const int c = i & 7;
        cp16(sbase + r * (TSTRIDE * 2) + c * 16,
             src + (size_t)(row_base + r) * DD + k0 + c * 8);
    }
}

__device__ __forceinline__ void load_stage(
    uint32_t sbase, const __half* Ahi,
    const __half* Whi, const __half* Wlo,
    int bm, int bn, int k0, int tid)
{
    load_tile_async(sbase + 0 * TILE_B, Ahi, bm, k0, tid);
    load_tile_async(sbase + 1 * TILE_B, Whi, bn, k0, tid);
    load_tile_async(sbase + 2 * TILE_B, Wlo, bn, k0, tid);
    cp_commit();
}

__device__ __forceinline__ void gemm_mainloop(
    char* sm, uint32_t sb,
    const __half* Ahi, const __half* Whi, const __half* Wlo,
    int bm, int bn, int tid, int wm, int wn, int g, int t,
    float acc[4][4][4])
{
    load_stage(sb + 0 * STAGE_B, Ahi, Whi, Wlo, bm, bn, 0, tid);
    load_stage(sb + 1 * STAGE_B, Ahi, Whi, Wlo, bm, bn, BK, tid);

    for (int kc = 0; kc < NKC; kc++) {
        if (kc + 2 < NKC) {
            load_stage(sb + ((kc + 2) % NSTAGE) * STAGE_B,
                       Ahi, Whi, Wlo, bm, bn, (kc + 2) * BK, tid);
            cp_wait<2>();
        } else if (kc + 1 < NKC) {
            cp_wait<1>();
        } else {
            cp_wait<0>();
        }
        __syncthreads();

        const char* stg = sm + (kc % NSTAGE) * STAGE_B;
        const char* tAhi = stg + 0 * TILE_B;
        const char* tWhi = stg + 1 * TILE_B;
        const char* tWlo = stg + 2 * TILE_B;

#pragma unroll
        for (int k16 = 0; k16 < 4; k16++) {
            const int k0 = k16 * 16;
            uint32_t ah[4][4], bh[4][2], bl[4][2];
#pragma unroll
            for (int mt = 0; mt < 4; mt++) {
                const int r0 = wm + mt * 16 + g;
                const int cA = k0 + 2 * t;
                ah[mt][0] = *(const uint32_t*)(tAhi + ((r0)     * TSTRIDE + cA)     * 2);
                ah[mt][1] = *(const uint32_t*)(tAhi + ((r0 + 8) * TSTRIDE + cA)     * 2);
                ah[mt][2] = *(const uint32_t*)(tAhi + ((r0)     * TSTRIDE + cA + 8) * 2);
                ah[mt][3] = *(const uint32_t*)(tAhi + ((r0 + 8) * TSTRIDE + cA + 8) * 2);
            }
#pragma unroll
            for (int nt = 0; nt < 4; nt++) {
                const int nr = wn + nt * 8 + g;
                const int cB = k0 + 2 * t;
                bh[nt][0] = *(const uint32_t*)(tWhi + (nr * TSTRIDE + cB)     * 2);
                bh[nt][1] = *(const uint32_t*)(tWhi + (nr * TSTRIDE + cB + 8) * 2);
                bl[nt][0] = *(const uint32_t*)(tWlo + (nr * TSTRIDE + cB)     * 2);
                bl[nt][1] = *(const uint32_t*)(tWlo + (nr * TSTRIDE + cB + 8) * 2);
            }
#pragma unroll
            for (int mt = 0; mt < 4; mt++)
#pragma unroll
                for (int nt = 0; nt < 4; nt++) {
                    float* c = acc[mt][nt];
                    mma_f16(c[0], c[1], c[2], c[3],
                            ah[mt][0], ah[mt][1], ah[mt][2], ah[mt][3],
                            bh[nt][0], bh[nt][1]);
                    mma_f16(c[0], c[1], c[2], c[3],
                            ah[mt][0], ah[mt][1], ah[mt][2], ah[mt][3],
                            bl[nt][0], bl[nt][1]);
                }
        }
        __syncthreads();
    }
}

// fused QKV projection GEMM: gridDim.z selects {Q, K, V}
__global__ __launch_bounds__(256) void qkv_gemm_kernel(
    const __half* __restrict__ xhi,
    const __half* __restrict__ whi, const __half* __restrict__ wlo,
    const float* __restrict__ bq, const float* __restrict__ bk,
    const float* __restrict__ bv,
    __half* __restrict__ qhi, __half* __restrict__ qlo,
    __half* __restrict__ khi, __half* __restrict__ klo,
    __half* __restrict__ vthi, __half* __restrict__ vtlo)
{
    extern __shared__ char sm[];
    const uint32_t sb = smem_u32(sm);
    const int tid = threadIdx.x;
    const int wid = tid >> 5;
    const int lid = tid & 31;
    const int g = lid >> 2;
    const int t = lid & 3;
    const int bm = blockIdx.y * 128;
    const int bn = blockIdx.x * 128;
    const int wm = (wid & 1) * 64;
    const int wn = (wid >> 1) * 32;
    const int z = blockIdx.z;

    const size_t Msz = (size_t)BB * SS * DD;
    const __half* Ahi = xhi + (size_t)z * Msz;
    const __half* Whi = whi + (size_t)z * DD * DD;
    const __half* Wlo = wlo + (size_t)z * DD * DD;
    const float* bias = (z == 0) ? bq : ((z == 1) ? bk : bv);
    __half* Ohi = (z == 0) ? qhi : ((z == 1) ? khi : vthi);
    __half* Olo = (z == 0) ? qlo : ((z == 1) ? klo : vtlo);

    float acc[4][4][4];
#pragma unroll
    for (int mt = 0; mt < 4; mt++)
#pragma unroll
        for (int nt = 0; nt < 4; nt++)
#pragma unroll
            for (int r = 0; r < 4; r++) acc[mt][nt][r] = 0.0f;

    gemm_mainloop(sm, sb, Ahi, Whi, Wlo, bm, bn, tid, wm, wn, g, t, acc);

    const bool trans = (z == 2);
#pragma unroll
    for (int mt = 0; mt < 4; mt++) {
#pragma unroll
        for (int nt = 0; nt < 4; nt++) {
            const float* c = acc[mt][nt];
            const int n0 = bn + wn + nt * 8 + 2 * t;
            const float bia0 = __ldg(&bias[n0]);
            const float bia1 = __ldg(&bias[n0 + 1]);
#pragma unroll
            for (int half = 0; half < 2; half++) {
                const int m = bm + wm + mt * 16 + g + half * 8;
                const float v0 = c[half * 2 + 0] + bia0;
                const float v1 = c[half * 2 + 1] + bia1;
                const int bidx = m >> 11;
                const int sidx = m & (SS - 1);
                const int h0 = n0 >> 6;
                const int dh = n0 & (DHH - 1);
                __half h_0 = __float2half_rn(v0);
                __half h_1 = __float2half_rn(v1);
                __half l_0 = __float2half_rn(v0 - __half2float(h_0));
                __half l_1 = __float2half_rn(v1 - __half2float(h_1));
                if (!trans) {
                    const size_t idx = (((size_t)bidx * HH + h0) * SS + sidx) * DHH + dh;
                    *(__half2*)(Ohi + idx) = __halves2half2(h_0, h_1);
                    *(__half2*)(Olo + idx) = __halves2half2(l_0, l_1);
                } else {
                    const size_t idx = (((size_t)bidx * HH + h0) * DHH + dh) * SS + sidx;
                    Ohi[idx] = h_0;
                    Ohi[idx + SS] = h_1;
                    Olo[idx] = l_0;
                    Olo[idx + SS] = l_1;
                }
            }
        }
    }
}

// O projection GEMM (fp32 row-major out)
__global__ __launch_bounds__(256) void o_gemm_kernel(
    const __half* __restrict__ Ahi,
    const __half* __restrict__ Whi, const __half* __restrict__ Wlo,
    const float* __restrict__ bias, float* __restrict__ C)
{
    extern __shared__ char sm[];
    const uint32_t sb = smem_u32(sm);
    const int tid = threadIdx.x;
    const int wid = tid >> 5;
    const int lid = tid & 31;
    const int g = lid >> 2;
    const int t = lid & 3;
    const int bm = blockIdx.y * 128;
    const int bn = blockIdx.x * 128;
    const int wm = (wid & 1) * 64;
    const int wn = (wid >> 1) * 32;

    float acc[4][4][4];
#pragma unroll
    for (int mt = 0; mt < 4; mt++)
#pragma unroll
        for (int nt = 0; nt < 4; nt++)
#pragma unroll
            for (int r = 0; r < 4; r++) acc[mt][nt][r] = 0.0f;

    gemm_mainloop(sm, sb, Ahi, Whi, Wlo, bm, bn, tid, wm, wn, g, t, acc);

#pragma unroll
    for (int mt = 0; mt < 4; mt++) {
#pragma unroll
        for (int nt = 0; nt < 4; nt++) {
            const float* c = acc[mt][nt];
            const int n0 = bn + wn + nt * 8 + 2 * t;
            const float bia0 = __ldg(&bias[n0]);
            const float bia1 = __ldg(&bias[n0 + 1]);
#pragma unroll
            for (int half = 0; half < 2; half++) {
                const int m = bm + wm + mt * 16 + g + half * 8;
                C[(size_t)m * DD + n0]     = c[half * 2 + 0] + bia0;
                C[(size_t)m * DD + n0 + 1] = c[half * 2 + 1] + bia1;
            }
        }
    }
}

// ---------------------------------------------------------------------------
// Tensor-core flash attention, fp16 2-term:
//   S = qh*(kh + kl);  O += ph*(vh + vl);  ctx emitted as fp16 (hi only)
// ---------------------------------------------------------------------------
#define KSTR 72
#define FTILE_B (64 * KSTR * 2)
#define FSTAGE_B (4 * FTILE_B)
#define FLASH_SMEM (2 * FSTAGE_B)

__global__ __launch_bounds__(128) void flash_tc_kernel(
    const __half* __restrict__ Qhi,
    const __half* __restrict__ Khi, const __half* __restrict__ Klo,
    const __half* __restrict__ VThi, const __half* __restrict__ VTlo,
    __half* __restrict__ Ctx)
{
    extern __shared__ char sm[];
    const uint32_t sb = smem_u32(sm);
    const int tid = threadIdx.x;
    const int wid = tid >> 5;
    const int lid = tid & 31;
    const int g = lid >> 2;
    const int t = lid & 3;
    const int qb = gridDim.x - 1 - blockIdx.x;
    const int bh = blockIdx.y;

    const size_t hoff = (size_t)bh * SS * DHH;
    const __half* qhi = Qhi + hoff;
    const __half* khi = Khi + hoff;
    const __half* klo = Klo + hoff;
    const __half* vthi = VThi + hoff;
    const __half* vtlo = VTlo + hoff;

    const int qrow0 = qb * 64 + wid * 16;

    uint32_t qh[4][4];
#pragma unroll
    for (int s = 0; s < 4; s++) {
        const int cA = s * 16 + 2 * t;
        qh[s][0] = *(const uint32_t*)(qhi + (size_t)(qrow0 + g)     * DHH + cA);
        qh[s][1] = *(const uint32_t*)(qhi + (size_t)(qrow0 + g + 8) * DHH + cA);
        qh[s][2] = *(const uint32_t*)(qhi + (size_t)(qrow0 + g)     * DHH + cA + 8);
        qh[s][3] = *(const uint32_t*)(qhi + (size_t)(qrow0 + g + 8) * DHH + cA + 8);
    }

    float oa[8][4];
#pragma unroll
    for (int j = 0; j < 8; j++)
#pragma unroll
        for (int r = 0; r < 4; r++) oa[j][r] = 0.0f;
    float mrun0 = -INFINITY, mrun1 = -INFINITY, lrun0 = 0.0f, lrun1 = 0.0f;

    auto load_kv = [&](int jb, int stage) {
        const uint32_t s0 = sb + stage * FSTAGE_B;
        const int kb = jb * 64;
#pragma unroll
        for (int p = 0; p < 4; p++) {
            const int i = p * 128 + tid;
            const int r = i >> 3;
            const int c = i & 7;
            const uint32_t d = r * (KSTR * 2) + c * 16;
            cp16(s0 + 0 * FTILE_B + d, khi  + (size_t)(kb + r) * DHH + c * 8);
            cp16(s0 + 1 * FTILE_B + d, klo  + (size_t)(kb + r) * DHH + c * 8);
            cp16(s0 + 2 * FTILE_B + d, vthi + (size_t)r * SS + kb + c * 8);
            cp16(s0 + 3 * FTILE_B + d, vtlo + (size_t)r * SS + kb + c * 8);
        }
    };

    load_kv(0, 0);
    cp_commit();

    const float scale = 0.125f;

    for (int jb = 0; jb <= qb; jb++) {
        const int s = jb & 1;
        if (jb < qb) {
            load_kv(jb + 1, s ^ 1);
            cp_commit();
            cp_wait<1>();
        } else {
            cp_wait<0>();
        }
        __syncthreads();

        const char* stg = sm + s * FSTAGE_B;
        const char* tKhi = stg + 0 * FTILE_B;
        const char* tKlo = stg + 1 * FTILE_B;
        const char* tVhi = stg + 2 * FTILE_B;
        const char* tVlo = stg + 3 * FTILE_B;

        // ---- S = qh*(kh + kl) ----
        float sacc[8][4];
#pragma unroll
        for (int j = 0; j < 8; j++)
#pragma unroll
            for (int r = 0; r < 4; r++) sacc[j][r] = 0.0f;

#pragma unroll
        for (int ks = 0; ks < 4; ks++) {
            const int cB = ks * 16 + 2 * t;
            uint32_t kbh[8][2], kbl[8][2];
#pragma unroll
            for (int j = 0; j < 8; j++) {
                const int nr = j * 8 + g;
                kbh[j][0] = *(const uint32_t*)(tKhi + (nr * KSTR + cB)     * 2);
                kbh[j][1] = *(const uint32_t*)(tKhi + (nr * KSTR + cB + 8) * 2);
                kbl[j][0] = *(const uint32_t*)(tKlo + (nr * KSTR + cB)     * 2);
                kbl[j][1] = *(const uint32_t*)(tKlo + (nr * KSTR + cB + 8) * 2);
            }
#pragma unroll
            for (int j = 0; j < 8; j++)
                mma_f16(sacc[j][0], sacc[j][1], sacc[j][2], sacc[j][3],
                        qh[ks][0], qh[ks][1], qh[ks][2], qh[ks][3],
                        kbh[j][0], kbh[j][1]);
#pragma unroll
            for (int j = 0; j < 8; j++)
                mma_f16(sacc[j][0], sacc[j][1], sacc[j][2], sacc[j][3],
                        qh[ks][0], qh[ks][1], qh[ks][2], qh[ks][3],
                        kbl[j][0], kbl[j][1]);
        }

        // ---- scale + causal mask ----
        const int qg0 = qrow0 + g;
        const int qg1 = qrow0 + g + 8;
        if (jb == qb) {
            const int kbase = jb * 64;
#pragma unroll
            for (int j = 0; j < 8; j++) {
                const int c0 = kbase + j * 8 + 2 * t;
                const int c1 = c0 + 1;
                sacc[j][0] = (c0 > qg0) ? -1e30f : sacc[j][0] * scale;
                sacc[j][1] = (c1 > qg0) ? -1e30f : sacc[j][1] * scale;
                sacc[j][2] = (c0 > qg1) ? -1e30f : sacc[j][2] * scale;
                sacc[j][3] = (c1 > qg1) ? -1e30f : sacc[j][3] * scale;
            }
        } else {
#pragma unroll
            for (int j = 0; j < 8; j++)
#pragma unroll
                for (int r = 0; r < 4; r++) sacc[j][r] *= scale;
        }

        // ---- online softmax ----
        float mt0 = -INFINITY, mt1 = -INFINITY;
#pragma unroll
        for (int j = 0; j < 8; j++) {
            mt0 = fmaxf(mt0, fmaxf(sacc[j][0], sacc[j][1]));
            mt1 = fmaxf(mt1, fmaxf(sacc[j][2], sacc[j][3]));
        }
        mt0 = fmaxf(mt0, __shfl_xor_sync(0xffffffffu, mt0, 1));
        mt0 = fmaxf(mt0, __shfl_xor_sync(0xffffffffu, mt0, 2));
        mt1 = fmaxf(mt1, __shfl_xor_sync(0xffffffffu, mt1, 1));
        mt1 = fmaxf(mt1, __shfl_xor_sync(0xffffffffu, mt1, 2));
        const float mn0 = fmaxf(mrun0, mt0);
        const float mn1 = fmaxf(mrun1, mt1);
        const float al0 = __expf(mrun0 - mn0);
        const float al1 = __expf(mrun1 - mn1);
        float rs0 = 0.0f, rs1 = 0.0f;
#pragma unroll
        for (int j = 0; j < 8; j++) {
            sacc[j][0] = __expf(sacc[j][0] - mn0);
            sacc[j][1] = __expf(sacc[j][1] - mn0);
            sacc[j][2] = __expf(sacc[j][2] - mn1);
            sacc[j][3] = __expf(sacc[j][3] - mn1);
            rs0 += sacc[j][0] + sacc[j][1];
            rs1 += sacc[j][2] + sacc[j][3];
        }
        rs0 += __shfl_xor_sync(0xffffffffu, rs0, 1);
        rs0 += __shfl_xor_sync(0xffffffffu, rs0, 2);
        rs1 += __shfl_xor_sync(0xffffffffu, rs1, 1);
        rs1 += __shfl_xor_sync(0xffffffffu, rs1, 2);
        lrun0 = al0 * lrun0 + rs0;
        lrun1 = al1 * lrun1 + rs1;
        mrun0 = mn0;
        mrun1 = mn1;
#pragma unroll
        for (int j = 0; j < 8; j++) {
            oa[j][0] *= al0;
            oa[j][1] *= al0;
            oa[j][2] *= al1;
            oa[j][3] *= al1;
        }

        // ---- O += ph*(vh + vl) ----
#pragma unroll
        for (int ks = 0; ks < 4; ks++) {
            const int j0 = 2 * ks, j1 = 2 * ks + 1;
            uint32_t pah[4];
            pah[0] = pack_f16x2(sacc[j0][0], sacc[j0][1]);
            pah[1] = pack_f16x2(sacc[j0][2], sacc[j0][3]);
            pah[2] = pack_f16x2(sacc[j1][0], sacc[j1][1]);
            pah[3] = pack_f16x2(sacc[j1][2], sacc[j1][3]);

            uint32_t vh[8][2], vl[8][2];
#pragma unroll
            for (int jd = 0; jd < 8; jd++) {
                const int nr = jd * 8 + g;
                const int cB = ks * 16 + 2 * t;
                vh[jd][0] = *(const uint32_t*)(tVhi + (nr * KSTR + cB)     * 2);
                vh[jd][1] = *(const uint32_t*)(tVhi + (nr * KSTR + cB + 8) * 2);
                vl[jd][0] = *(const uint32_t*)(tVlo + (nr * KSTR + cB)     * 2);
                vl[jd][1] = *(const uint32_t*)(tVlo + (nr * KSTR + cB + 8) * 2);
            }
#pragma unroll
            for (int jd = 0; jd < 8; jd++)
                mma_f16(oa[jd][0], oa[jd][1], oa[jd][2], oa[jd][3],
                        pah[0], pah[1], pah[2], pah[3], vh[jd][0], vh[jd][1]);
#pragma unroll
            for (int jd = 0; jd < 8; jd++)
                mma_f16(oa[jd][0], oa[jd][1], oa[jd][2], oa[jd][3],
                        pah[0], pah[1], pah[2], pah[3], vl[jd][0], vl[jd][1]);
        }
        __syncthreads();
    }

    // finalize: ctx as fp16 (hi only) in [B,S,D]
    const int b = bh >> 4;
    const int h = bh & 15;
    const float inv0 = 1.0f / lrun0;
    const float inv1 = 1.0f / lrun1;
#pragma unroll
    for (int jd = 0; jd < 8; jd++) {
        const int dh = jd * 8 + 2 * t;
        const size_t idx0 = ((size_t)b * SS + qrow0 + g)     * DD + h * DHH + dh;
        const size_t idx1 = ((size_t)b * SS + qrow0 + g + 8) * DD + h * DHH + dh;
        *(__half2*)(Ctx + idx0) =
            __floats2half2_rn(oa[jd][0] * inv0, oa[jd][1] * inv0);
        *(__half2*)(Ctx + idx1) =
            __floats2half2_rn(oa[jd][2] * inv1, oa[jd][3] * inv1);
    }
}

// ---------------------------------------------------------------------------
// Launch
// ---------------------------------------------------------------------------
extern "C" void kernel_launch(void* const* d_in, const int* in_sizes, int n_in,
                              void* d_out, int out_size)
{
    const float* query = (const float*)d_in[0];
    const float* key_i = (const float*)d_in[1];
    const float* value = (const float*)d_in[2];
    const float* Wq = (const float*)d_in[4];
    const float* bq = (const float*)d_in[5];
    const float* Wk = (const float*)d_in[6];
    const float* bk = (const float*)d_in[7];
    const float* Wv = (const float*)d_in[8];
    const float* bv = (const float*)d_in[9];
    const float* Wo = (const float*)d_in[10];
    const float* bo = (const float*)d_in[11];
    float* out = (float*)d_out;

    __half *xhi, *whi, *wlo;
    __half *qhi, *qlo, *khi, *klo, *vthi, *vtlo;
    cudaGetSymbolAddress((void**)&xhi, g_xhi);
    cudaGetSymbolAddress((void**)&whi, g_whi);
    cudaGetSymbolAddress((void**)&wlo, g_wlo);
    cudaGetSymbolAddress((void**)&qhi, g_qhi);
    cudaGetSymbolAddress((void**)&qlo, g_qlo);
    cudaGetSymbolAddress((void**)&khi, g_khi);
    cudaGetSymbolAddress((void**)&klo, g_klo);
    cudaGetSymbolAddress((void**)&vthi, g_vthi);
    cudaGetSymbolAddress((void**)&vtlo, g_vtlo);

    const int M = BB * SS;
    const int nX4 = M * DD / 4;
    const int nW4 = DD * DD / 4;

    cudaFuncSetAttribute(qkv_gemm_kernel,
                         cudaFuncAttributeMaxDynamicSharedMemorySize, GEMM_SMEM);
    cudaFuncSetAttribute(o_gemm_kernel,
                         cudaFuncAttributeMaxDynamicSharedMemorySize, GEMM_SMEM);
    cudaFuncSetAttribute(flash_tc_kernel,
                         cudaFuncAttributeMaxDynamicSharedMemorySize, FLASH_SMEM);

    // splits
    split_x3_kernel<<<dim3((nX4 + 255) / 256, 3), 256>>>(
        query, key_i, value, xhi, nX4);
    split_w4_kernel<<<dim3((nW4 + 255) / 256, 4), 256>>>(
        Wq, Wk, Wv, Wo, whi, wlo, nW4);

    // fused QKV projections (z = 0,1,2)
    qkv_gemm_kernel<<<dim3(DD / 128, M / 128, 3), 256, GEMM_SMEM>>>(
        xhi, whi, wlo, bq, bk, bv,
        qhi, qlo, khi, klo, vthi, vtlo);

    // flash attention -> ctx fp16 into xhi slot 0
    flash_tc_kernel<<<dim3(SS / 64, BB * HH), 128, FLASH_SMEM>>>(
        qhi, khi, klo, vthi, vtlo, xhi);

    // O projection
    o_gemm_kernel<<<dim3(DD / 128, M / 128), 256, GEMM_SMEM>>>(
        xhi, whi + (size_t)3 * DD * DD, wlo + (size_t)3 * DD * DD, bo, out);
}

// round 11
// speedup vs baseline: 2.4904x; 1.1880x over previous
#include <cuda_runtime.h>
#include <cuda_fp16.h>
#include <math.h>
#include <stdint.h>

#define BB 4
#define SS 2048
#define DD 1024
#define HH 16
#define DHH 64

// ---------------------------------------------------------------------------
// Scratch (allocation-free __device__ globals)
// ---------------------------------------------------------------------------
__device__ __half g_xhi[3 * BB * SS * DD];   // q/k/v GEMM A (hi); slot0 reused for ctx
__device__ __half g_whi[4 * DD * DD];        // Wq,Wk,Wv,Wo hi
__device__ __half g_wlo[4 * DD * DD];        // lo
__device__ __half g_qh[BB * SS * DD];        // [B,H,S,DH]
__device__ __half g_kh[BB * SS * DD];        // [B,H,S,DH]
__device__ __half g_vth[BB * SS * DD];       // [B,H,DH,S]

// ---------------------------------------------------------------------------
// helpers
// ---------------------------------------------------------------------------
__device__ __forceinline__ uint32_t smem_u32(const void* p) {
    uint32_t a;
    asm("{ .reg .u64 t; cvta.to.shared.u64 t, %1; cvt.u32.u64 %0, t; }"
        : "=r"(a) : "l"(p));
    return a;
}
__device__ __forceinline__ void cp16(uint32_t sdst, const void* gsrc) {
    asm volatile("cp.async.cg.shared.global [%0], [%1], 16;"
                 :: "r"(sdst), "l"(gsrc));
}
__device__ __forceinline__ void cp_commit() {
    asm volatile("cp.async.commit_group;");
}
template <int N>
__device__ __forceinline__ void cp_wait() {
    asm volatile("cp.async.wait_group %0;" :: "n"(N));
}
__device__ __forceinline__ void mma_f16(float& c0, float& c1, float& c2, float& c3,
                                        uint32_t a0, uint32_t a1, uint32_t a2, uint32_t a3,
                                        uint32_t b0, uint32_t b1) {
    asm volatile(
        "mma.sync.aligned.m16n8k16.row.col.f32.f16.f16.f32 "
        "{%0,%1,%2,%3}, {%4,%5,%6,%7}, {%8,%9}, {%0,%1,%2,%3};"
        : "+f"(c0), "+f"(c1), "+f"(c2), "+f"(c3)
        : "r"(a0), "r"(a1), "r"(a2), "r"(a3), "r"(b0), "r"(b1));
}
__device__ __forceinline__ uint32_t pack_f16x2(float a, float b) {
    __half2 h = __floats2half2_rn(a, b);
    return *(uint32_t*)&h;
}

// ---------------------------------------------------------------------------
// splits
// ---------------------------------------------------------------------------
__global__ __launch_bounds__(256) void split_x3_kernel(
    const float* __restrict__ x0, const float* __restrict__ x1,
    const float* __restrict__ x2, __half* __restrict__ hi, int n4)
{
    const int z = blockIdx.y;
    const float* x = (z == 0) ? x0 : ((z == 1) ? x1 : x2);
    int i = blockIdx.x * blockDim.x + threadIdx.x;
    if (i >= n4) return;
    float4 v = ((const float4*)x)[i];
    __half2* hp = (__half2*)(hi + (size_t)z * n4 * 4 + (size_t)i * 4);
    hp[0] = __floats2half2_rn(v.x, v.y);
    hp[1] = __floats2half2_rn(v.z, v.w);
}

__global__ __launch_bounds__(256) void split_w4_kernel(
    const float* __restrict__ w0, const float* __restrict__ w1,
    const float* __restrict__ w2, const float* __restrict__ w3,
    __half* __restrict__ hi, __half* __restrict__ lo, int n4)
{
    const int z = blockIdx.y;
    const float* w = (z == 0) ? w0 : ((z == 1) ? w1 : ((z == 2) ? w2 : w3));
    int i = blockIdx.x * blockDim.x + threadIdx.x;
    if (i >= n4) return;
    float4 v = ((const float4*)w)[i];
    __half h0 = __float2half_rn(v.x);
    __half h1 = __float2half_rn(v.y);
    __half h2 = __float2half_rn(v.z);
    __half h3 = __float2half_rn(v.w);
    __half l0 = __float2half_rn(v.x - __half2float(h0));
    __half l1 = __float2half_rn(v.y - __half2float(h1));
    __half l2 = __float2half_rn(v.z - __half2float(h2));
    __half l3 = __float2half_rn(v.w - __half2float(h3));
    __half2* hp = (__half2*)(hi + (size_t)z * n4 * 4 + (size_t)i * 4);
    __half2* lp = (__half2*)(lo + (size_t)z * n4 * 4 + (size_t)i * 4);
    hp[0] = __halves2half2(h0, h1);
    hp[1] = __halves2half2(h2, h3);
    lp[0] = __halves2half2(l0, l1);
    lp[1] = __halves2half2(l2, l3);
}

// ---------------------------------------------------------------------------
// GEMM: CTA 128x128, 256 thr (8 warps, 2M x 4N), BK=64, 3-stage cp.async.
// 2-term: C = Ah*(Wh + Wl) in fp32 acc. Stage = {Ah, Wh, Wl}.
// ---------------------------------------------------------------------------
#define BK 64
#define NKC (DD / BK)
#define TSTRIDE 72
#define TILE_B (128 * TSTRIDE * 2)
#define STAGE_B (3 * TILE_B)
#define NSTAGE 3
#define GEMM_SMEM (NSTAGE * STAGE_B)

__device__ __forceinline__ void load_tile_async(
    uint32_t sbase, const __half* __restrict__ src,
    int row_base, int k0, int tid)
{
#pragma unroll
    for (int p = 0; p < 4; p++) {
        const int i = p * 256 + tid;
        const int r = i >> 3;
        const int c = i & 7;
        cp16(sbase + r * (TSTRIDE * 2) + c * 16,
             src + (size_t)(row_base + r) * DD + k0 + c * 8);
    }
}

__device__ __forceinline__ void load_stage(
    uint32_t sbase, const __half* Ahi,
    const __half* Whi, const __half* Wlo,
    int bm, int bn, int k0, int tid)
{
    load_tile_async(sbase + 0 * TILE_B, Ahi, bm, k0, tid);
    load_tile_async(sbase + 1 * TILE_B, Whi, bn, k0, tid);
    load_tile_async(sbase + 2 * TILE_B, Wlo, bn, k0, tid);
    cp_commit();
}

__device__ __forceinline__ void gemm_mainloop(
    char* sm, uint32_t sb,
    const __half* Ahi, const __half* Whi, const __half* Wlo,
    int bm, int bn, int tid, int wm, int wn, int g, int t,
    float acc[4][4][4])
{
    load_stage(sb + 0 * STAGE_B, Ahi, Whi, Wlo, bm, bn, 0, tid);
    load_stage(sb + 1 * STAGE_B, Ahi, Whi, Wlo, bm, bn, BK, tid);

    for (int kc = 0; kc < NKC; kc++) {
        if (kc + 2 < NKC) {
            load_stage(sb + ((kc + 2) % NSTAGE) * STAGE_B,
                       Ahi, Whi, Wlo, bm, bn, (kc + 2) * BK, tid);
            cp_wait<2>();
        } else if (kc + 1 < NKC) {
            cp_wait<1>();
        } else {
            cp_wait<0>();
        }
        __syncthreads();

        const char* stg = sm + (kc % NSTAGE) * STAGE_B;
        const char* tAhi = stg + 0 * TILE_B;
        const char* tWhi = stg + 1 * TILE_B;
        const char* tWlo = stg + 2 * TILE_B;

#pragma unroll
        for (int k16 = 0; k16 < 4; k16++) {
            const int k0 = k16 * 16;
            uint32_t ah[4][4], bh[4][2], bl[4][2];
#pragma unroll
            for (int mt = 0; mt < 4; mt++) {
                const int r0 = wm + mt * 16 + g;
                const int cA = k0 + 2 * t;
                ah[mt][0] = *(const uint32_t*)(tAhi + ((r0)     * TSTRIDE + cA)     * 2);
                ah[mt][1] = *(const uint32_t*)(tAhi + ((r0 + 8) * TSTRIDE + cA)     * 2);
                ah[mt][2] = *(const uint32_t*)(tAhi + ((r0)     * TSTRIDE + cA + 8) * 2);
                ah[mt][3] = *(const uint32_t*)(tAhi + ((r0 + 8) * TSTRIDE + cA + 8) * 2);
            }
#pragma unroll
            for (int nt = 0; nt < 4; nt++) {
                const int nr = wn + nt * 8 + g;
                const int cB = k0 + 2 * t;
                bh[nt][0] = *(const uint32_t*)(tWhi + (nr * TSTRIDE + cB)     * 2);
                bh[nt][1] = *(const uint32_t*)(tWhi + (nr * TSTRIDE + cB + 8) * 2);
                bl[nt][0] = *(const uint32_t*)(tWlo + (nr * TSTRIDE + cB)     * 2);
                bl[nt][1] = *(const uint32_t*)(tWlo + (nr * TSTRIDE + cB + 8) * 2);
            }
#pragma unroll
            for (int mt = 0; mt < 4; mt++)
#pragma unroll
                for (int nt = 0; nt < 4; nt++) {
                    float* c = acc[mt][nt];
                    mma_f16(c[0], c[1], c[2], c[3],
                            ah[mt][0], ah[mt][1], ah[mt][2], ah[mt][3],
                            bh[nt][0], bh[nt][1]);
                    mma_f16(c[0], c[1], c[2], c[3],
                            ah[mt][0], ah[mt][1], ah[mt][2], ah[mt][3],
                            bl[nt][0], bl[nt][1]);
                }
        }
        __syncthreads();
    }
}

// fused QKV projection GEMM: gridDim.z selects {Q, K, V}; fp16 hi-only outputs
__global__ __launch_bounds__(256) void qkv_gemm_kernel(
    const __half* __restrict__ xhi,
    const __half* __restrict__ whi, const __half* __restrict__ wlo,
    const float* __restrict__ bq, const float* __restrict__ bk,
    const float* __restrict__ bv,
    __half* __restrict__ qh, __half* __restrict__ kh,
    __half* __restrict__ vth)
{
    extern __shared__ char sm[];
    const uint32_t sb = smem_u32(sm);
    const int tid = threadIdx.x;
    const int wid = tid >> 5;
    const int lid = tid & 31;
    const int g = lid >> 2;
    const int t = lid & 3;
    const int bm = blockIdx.y * 128;
    const int bn = blockIdx.x * 128;
    const int wm = (wid & 1) * 64;
    const int wn = (wid >> 1) * 32;
    const int z = blockIdx.z;

    const size_t Msz = (size_t)BB * SS * DD;
    const __half* Ahi = xhi + (size_t)z * Msz;
    const __half* Whi = whi + (size_t)z * DD * DD;
    const __half* Wlo = wlo + (size_t)z * DD * DD;
    const float* bias = (z == 0) ? bq : ((z == 1) ? bk : bv);
    __half* Oh = (z == 0) ? qh : ((z == 1) ? kh : vth);

    float acc[4][4][4];
#pragma unroll
    for (int mt = 0; mt < 4; mt++)
#pragma unroll
        for (int nt = 0; nt < 4; nt++)
#pragma unroll
            for (int r = 0; r < 4; r++) acc[mt][nt][r] = 0.0f;

    gemm_mainloop(sm, sb, Ahi, Whi, Wlo, bm, bn, tid, wm, wn, g, t, acc);

    const bool trans = (z == 2);
#pragma unroll
    for (int mt = 0; mt < 4; mt++) {
#pragma unroll
        for (int nt = 0; nt < 4; nt++) {
            const float* c = acc[mt][nt];
            const int n0 = bn + wn + nt * 8 + 2 * t;
            const float bia0 = __ldg(&bias[n0]);
            const float bia1 = __ldg(&bias[n0 + 1]);
#pragma unroll
            for (int half = 0; half < 2; half++) {
                const int m = bm + wm + mt * 16 + g + half * 8;
                const float v0 = c[half * 2 + 0] + bia0;
                const float v1 = c[half * 2 + 1] + bia1;
                const int bidx = m >> 11;
                const int sidx = m & (SS - 1);
                const int h0 = n0 >> 6;
                const int dh = n0 & (DHH - 1);
                if (!trans) {
                    const size_t idx = (((size_t)bidx * HH + h0) * SS + sidx) * DHH + dh;
                    *(__half2*)(Oh + idx) = __floats2half2_rn(v0, v1);
                } else {
                    const size_t idx = (((size_t)bidx * HH + h0) * DHH + dh) * SS + sidx;
                    Oh[idx] = __float2half_rn(v0);
                    Oh[idx + SS] = __float2half_rn(v1);
                }
            }
        }
    }
}

// O projection GEMM (fp32 row-major out)
__global__ __launch_bounds__(256) void o_gemm_kernel(
    const __half* __restrict__ Ahi,
    const __half* __restrict__ Whi, const __half* __restrict__ Wlo,
    const float* __restrict__ bias, float* __restrict__ C)
{
    extern __shared__ char sm[];
    const uint32_t sb = smem_u32(sm);
    const int tid = threadIdx.x;
    const int wid = tid >> 5;
    const int lid = tid & 31;
    const int g = lid >> 2;
    const int t = lid & 3;
    const int bm = blockIdx.y * 128;
    const int bn = blockIdx.x * 128;
    const int wm = (wid & 1) * 64;
    const int wn = (wid >> 1) * 32;

    float acc[4][4][4];
#pragma unroll
    for (int mt = 0; mt < 4; mt++)
#pragma unroll
        for (int nt = 0; nt < 4; nt++)
#pragma unroll
            for (int r = 0; r < 4; r++) acc[mt][nt][r] = 0.0f;

    gemm_mainloop(sm, sb, Ahi, Whi, Wlo, bm, bn, tid, wm, wn, g, t, acc);

#pragma unroll
    for (int mt = 0; mt < 4; mt++) {
#pragma unroll
        for (int nt = 0; nt < 4; nt++) {
            const float* c = acc[mt][nt];
            const int n0 = bn + wn + nt * 8 + 2 * t;
            const float bia0 = __ldg(&bias[n0]);
            const float bia1 = __ldg(&bias[n0 + 1]);
#pragma unroll
            for (int half = 0; half < 2; half++) {
                const int m = bm + wm + mt * 16 + g + half * 8;
                C[(size_t)m * DD + n0]     = c[half * 2 + 0] + bia0;
                C[(size_t)m * DD + n0 + 1] = c[half * 2 + 1] + bia1;
            }
        }
    }
}

// ---------------------------------------------------------------------------
// Tensor-core flash attention, pure fp16 operands:
//   S = qh*kh;  O += ph*vh;  ctx fp16 out.
// Stage = {K, VT} tiles (2 x 9216 B); 2 stages -> 36,864 B smem/CTA.
// ---------------------------------------------------------------------------
#define KSTR 72
#define FTILE_B (64 * KSTR * 2)
#define FSTAGE_B (2 * FTILE_B)
#define FLASH_SMEM (2 * FSTAGE_B)   // 36864

__global__ __launch_bounds__(128) void flash_tc_kernel(
    const __half* __restrict__ Qh,
    const __half* __restrict__ Kh,
    const __half* __restrict__ VTh,
    __half* __restrict__ Ctx)
{
    extern __shared__ char sm[];
    const uint32_t sb = smem_u32(sm);
    const int tid = threadIdx.x;
    const int wid = tid >> 5;
    const int lid = tid & 31;
    const int g = lid >> 2;
    const int t = lid & 3;
    const int qb = gridDim.x - 1 - blockIdx.x;
    const int bh = blockIdx.y;

    const size_t hoff = (size_t)bh * SS * DHH;
    const __half* qh = Qh + hoff;
    const __half* kh = Kh + hoff;
    const __half* vth = VTh + hoff;

    const int qrow0 = qb * 64 + wid * 16;

    uint32_t qf[4][4];
#pragma unroll
    for (int s = 0; s < 4; s++) {
        const int cA = s * 16 + 2 * t;
        qf[s][0] = *(const uint32_t*)(qh + (size_t)(qrow0 + g)     * DHH + cA);
        qf[s][1] = *(const uint32_t*)(qh + (size_t)(qrow0 + g + 8) * DHH + cA);
        qf[s][2] = *(const uint32_t*)(qh + (size_t)(qrow0 + g)     * DHH + cA + 8);
        qf[s][3] = *(const uint32_t*)(qh + (size_t)(qrow0 + g + 8) * DHH + cA + 8);
    }

    float oa[8][4];
#pragma unroll
    for (int j = 0; j < 8; j++)
#pragma unroll
        for (int r = 0; r < 4; r++) oa[j][r] = 0.0f;
    float mrun0 = -INFINITY, mrun1 = -INFINITY, lrun0 = 0.0f, lrun1 = 0.0f;

    auto load_kv = [&](int jb, int stage) {
        const uint32_t s0 = sb + stage * FSTAGE_B;
        const int kb = jb * 64;
#pragma unroll
        for (int p = 0; p < 4; p++) {
            const int i = p * 128 + tid;
            const int r = i >> 3;
            const int c = i & 7;
            const uint32_t d = r * (KSTR * 2) + c * 16;
            cp16(s0 + 0 * FTILE_B + d, kh  + (size_t)(kb + r) * DHH + c * 8);
            cp16(s0 + 1 * FTILE_B + d, vth + (size_t)r * SS + kb + c * 8);
        }
    };

    load_kv(0, 0);
    cp_commit();

    const float scale = 0.125f;

    for (int jb = 0; jb <= qb; jb++) {
        const int s = jb & 1;
        if (jb < qb) {
            load_kv(jb + 1, s ^ 1);
            cp_commit();
            cp_wait<1>();
        } else {
            cp_wait<0>();
        }
        __syncthreads();

        const char* stg = sm + s * FSTAGE_B;
        const char* tKh = stg + 0 * FTILE_B;
        const char* tVh = stg + 1 * FTILE_B;

        // ---- S = qh * kh ----
        float sacc[8][4];
#pragma unroll
        for (int j = 0; j < 8; j++)
#pragma unroll
            for (int r = 0; r < 4; r++) sacc[j][r] = 0.0f;

#pragma unroll
        for (int ks = 0; ks < 4; ks++) {
            const int cB = ks * 16 + 2 * t;
            uint32_t kb0[8], kb1[8];
#pragma unroll
            for (int j = 0; j < 8; j++) {
                const int nr = j * 8 + g;
                kb0[j] = *(const uint32_t*)(tKh + (nr * KSTR + cB)     * 2);
                kb1[j] = *(const uint32_t*)(tKh + (nr * KSTR + cB + 8) * 2);
            }
#pragma unroll
            for (int j = 0; j < 8; j++)
                mma_f16(sacc[j][0], sacc[j][1], sacc[j][2], sacc[j][3],
                        qf[ks][0], qf[ks][1], qf[ks][2], qf[ks][3],
                        kb0[j], kb1[j]);
        }

        // ---- scale + causal mask ----
        const int qg0 = qrow0 + g;
        const int qg1 = qrow0 + g + 8;
        if (jb == qb) {
            const int kbase = jb * 64;
#pragma unroll
            for (int j = 0; j < 8; j++) {
                const int c0 = kbase + j * 8 + 2 * t;
                const int c1 = c0 + 1;
                sacc[j][0] = (c0 > qg0) ? -1e30f : sacc[j][0] * scale;
                sacc[j][1] = (c1 > qg0) ? -1e30f : sacc[j][1] * scale;
                sacc[j][2] = (c0 > qg1) ? -1e30f : sacc[j][2] * scale;
                sacc[j][3] = (c1 > qg1) ? -1e30f : sacc[j][3] * scale;
            }
        } else {
#pragma unroll
            for (int j = 0; j < 8; j++)
#pragma unroll
                for (int r = 0; r < 4; r++) sacc[j][r] *= scale;
        }

        // ---- online softmax ----
        float mt0 = -INFINITY, mt1 = -INFINITY;
#pragma unroll
        for (int j = 0; j < 8; j++) {
            mt0 = fmaxf(mt0, fmaxf(sacc[j][0], sacc[j][1]));
            mt1 = fmaxf(mt1, fmaxf(sacc[j][2], sacc[j][3]));
        }
        mt0 = fmaxf(mt0, __shfl_xor_sync(0xffffffffu, mt0, 1));
        mt0 = fmaxf(mt0, __shfl_xor_sync(0xffffffffu, mt0, 2));
        mt1 = fmaxf(mt1, __shfl_xor_sync(0xffffffffu, mt1, 1));
        mt1 = fmaxf(mt1, __shfl_xor_sync(0xffffffffu, mt1, 2));
        const float mn0 = fmaxf(mrun0, mt0);
        const float mn1 = fmaxf(mrun1, mt1);
        const float al0 = __expf(mrun0 - mn0);
        const float al1 = __expf(mrun1 - mn1);
        float rs0 = 0.0f, rs1 = 0.0f;
#pragma unroll
        for (int j = 0; j < 8; j++) {
            sacc[j][0] = __expf(sacc[j][0] - mn0);
            sacc[j][1] = __expf(sacc[j][1] - mn0);
            sacc[j][2] = __expf(sacc[j][2] - mn1);
            sacc[j][3] = __expf(sacc[j][3] - mn1);
            rs0 += sacc[j][0] + sacc[j][1];
            rs1 += sacc[j][2] + sacc[j][3];
        }
        rs0 += __shfl_xor_sync(0xffffffffu, rs0, 1);
        rs0 += __shfl_xor_sync(0xffffffffu, rs0, 2);
        rs1 += __shfl_xor_sync(0xffffffffu, rs1, 1);
        rs1 += __shfl_xor_sync(0xffffffffu, rs1, 2);
        lrun0 = al0 * lrun0 + rs0;
        lrun1 = al1 * lrun1 + rs1;
        mrun0 = mn0;
        mrun1 = mn1;
#pragma unroll
        for (int j = 0; j < 8; j++) {
            oa[j][0] *= al0;
            oa[j][1] *= al0;
            oa[j][2] *= al1;
            oa[j][3] *= al1;
        }

        // ---- O += ph * vh ----
#pragma unroll
        for (int ks = 0; ks < 4; ks++) {
            const int j0 = 2 * ks, j1 = 2 * ks + 1;
            uint32_t pah[4];
            pah[0] = pack_f16x2(sacc[j0][0], sacc[j0][1]);
            pah[1] = pack_f16x2(sacc[j0][2], sacc[j0][3]);
            pah[2] = pack_f16x2(sacc[j1][0], sacc[j1][1]);
            pah[3] = pack_f16x2(sacc[j1][2], sacc[j1][3]);

            uint32_t vb0[8], vb1[8];
#pragma unroll
            for (int jd = 0; jd < 8; jd++) {
                const int nr = jd * 8 + g;
                const int cB = ks * 16 + 2 * t;
                vb0[jd] = *(const uint32_t*)(tVh + (nr * KSTR + cB)     * 2);
                vb1[jd] = *(const uint32_t*)(tVh + (nr * KSTR + cB + 8) * 2);
            }
#pragma unroll
            for (int jd = 0; jd < 8; jd++)
                mma_f16(oa[jd][0], oa[jd][1], oa[jd][2], oa[jd][3],
                        pah[0], pah[1], pah[2], pah[3], vb0[jd], vb1[jd]);
        }
        __syncthreads();
    }

    // finalize: ctx fp16 in [B,S,D]
    const int b = bh >> 4;
    const int h = bh & 15;
    const float inv0 = 1.0f / lrun0;
    const float inv1 = 1.0f / lrun1;
#pragma unroll
    for (int jd = 0; jd < 8; jd++) {
        const int dh = jd * 8 + 2 * t;
        const size_t idx0 = ((size_t)b * SS + qrow0 + g)     * DD + h * DHH + dh;
        const size_t idx1 = ((size_t)b * SS + qrow0 + g + 8) * DD + h * DHH + dh;
        *(__half2*)(Ctx + idx0) =
            __floats2half2_rn(oa[jd][0] * inv0, oa[jd][1] * inv0);
        *(__half2*)(Ctx + idx1) =
            __floats2half2_rn(oa[jd][2] * inv1, oa[jd][3] * inv1);
    }
}

// ---------------------------------------------------------------------------
// Launch
// ---------------------------------------------------------------------------
extern "C" void kernel_launch(void* const* d_in, const int* in_sizes, int n_in,
                              void* d_out, int out_size)
{
    const float* query = (const float*)d_in[0];
    const float* key_i = (const float*)d_in[1];
    const float* value = (const float*)d_in[2];
    const float* Wq = (const float*)d_in[4];
    const float* bq = (const float*)d_in[5];
    const float* Wk = (const float*)d_in[6];
    const float* bk = (const float*)d_in[7];
    const float* Wv = (const float*)d_in[8];
    const float* bv = (const float*)d_in[9];
    const float* Wo = (const float*)d_in[10];
    const float* bo = (const float*)d_in[11];
    float* out = (float*)d_out;

    __half *xhi, *whi, *wlo, *qh, *kh, *vth;
    cudaGetSymbolAddress((void**)&xhi, g_xhi);
    cudaGetSymbolAddress((void**)&whi, g_whi);
    cudaGetSymbolAddress((void**)&wlo, g_wlo);
    cudaGetSymbolAddress((void**)&qh, g_qh);
    cudaGetSymbolAddress((void**)&kh, g_kh);
    cudaGetSymbolAddress((void**)&vth, g_vth);

    const int M = BB * SS;
    const int nX4 = M * DD / 4;
    const int nW4 = DD * DD / 4;

    cudaFuncSetAttribute(qkv_gemm_kernel,
                         cudaFuncAttributeMaxDynamicSharedMemorySize, GEMM_SMEM);
    cudaFuncSetAttribute(o_gemm_kernel,
                         cudaFuncAttributeMaxDynamicSharedMemorySize, GEMM_SMEM);
    cudaFuncSetAttribute(flash_tc_kernel,
                         cudaFuncAttributeMaxDynamicSharedMemorySize, FLASH_SMEM);

    // splits
    split_x3_kernel<<<dim3((nX4 + 255) / 256, 3), 256>>>(
        query, key_i, value, xhi, nX4);
    split_w4_kernel<<<dim3((nW4 + 255) / 256, 4), 256>>>(
        Wq, Wk, Wv, Wo, whi, wlo, nW4);

    // fused QKV projections (z = 0,1,2)
    qkv_gemm_kernel<<<dim3(DD / 128, M / 128, 3), 256, GEMM_SMEM>>>(
        xhi, whi, wlo, bq, bk, bv, qh, kh, vth);

    // flash attention -> ctx fp16 into xhi slot 0
    flash_tc_kernel<<<dim3(SS / 64, BB * HH), 128, FLASH_SMEM>>>(
        qh, kh, vth, xhi);

    // O projection
    o_gemm_kernel<<<dim3(DD / 128, M / 128), 256, GEMM_SMEM>>>(
        xhi, whi + (size_t)3 * DD * DD, wlo + (size_t)3 * DD * DD, bo, out);
}

// round 12
// speedup vs baseline: 3.6095x; 1.4494x over previous
#include <cuda_runtime.h>
#include <cuda_fp16.h>
#include <math.h>
#include <stdint.h>

#define BB 4
#define SS 2048
#define DD 1024
#define HH 16
#define DHH 64

// ---------------------------------------------------------------------------
// Scratch (allocation-free __device__ globals)
// ---------------------------------------------------------------------------
__device__ __half g_xhi[3 * BB * SS * DD];   // q/k/v GEMM A (hi); slot0 reused for ctx
__device__ __half g_whi[4 * DD * DD];        // Wq,Wk,Wv,Wo (fp16)
__device__ __half g_qh[BB * SS * DD];        // [B,H,S,DH]
__device__ __half g_kh[BB * SS * DD];        // [B,H,S,DH]
__device__ __half g_vth[BB * SS * DD];       // [B,H,DH,S]

// ---------------------------------------------------------------------------
// helpers
// ---------------------------------------------------------------------------
__device__ __forceinline__ uint32_t smem_u32(const void* p) {
    uint32_t a;
    asm("{ .reg .u64 t; cvta.to.shared.u64 t, %1; cvt.u32.u64 %0, t; }"
        : "=r"(a) : "l"(p));
    return a;
}
__device__ __forceinline__ void cp16(uint32_t sdst, const void* gsrc) {
    asm volatile("cp.async.cg.shared.global [%0], [%1], 16;"
                 :: "r"(sdst), "l"(gsrc));
}
__device__ __forceinline__ void cp_commit() {
    asm volatile("cp.async.commit_group;");
}
template <int N>
__device__ __forceinline__ void cp_wait() {
    asm volatile("cp.async.wait_group %0;" :: "n"(N));
}
__device__ __forceinline__ void mma_f16(float& c0, float& c1, float& c2, float& c3,
                                        uint32_t a0, uint32_t a1, uint32_t a2, uint32_t a3,
                                        uint32_t b0, uint32_t b1) {
    asm volatile(
        "mma.sync.aligned.m16n8k16.row.col.f32.f16.f16.f32 "
        "{%0,%1,%2,%3}, {%4,%5,%6,%7}, {%8,%9}, {%0,%1,%2,%3};"
        : "+f"(c0), "+f"(c1), "+f"(c2), "+f"(c3)
        : "r"(a0), "r"(a1), "r"(a2), "r"(a3), "r"(b0), "r"(b1));
}
__device__ __forceinline__ uint32_t pack_f16x2(float a, float b) {
    __half2 h = __floats2half2_rn(a, b);
    return *(uint32_t*)&h;
}

// ---------------------------------------------------------------------------
// splits (fp32 -> fp16)
// ---------------------------------------------------------------------------
__global__ __launch_bounds__(256) void split_x3_kernel(
    const float* __restrict__ x0, const float* __restrict__ x1,
    const float* __restrict__ x2, __half* __restrict__ hi, int n4)
{
    const int z = blockIdx.y;
    const float* x = (z == 0) ? x0 : ((z == 1) ? x1 : x2);
    int i = blockIdx.x * blockDim.x + threadIdx.x;
    if (i >= n4) return;
    float4 v = ((const float4*)x)[i];
    __half2* hp = (__half2*)(hi + (size_t)z * n4 * 4 + (size_t)i * 4);
    hp[0] = __floats2half2_rn(v.x, v.y);
    hp[1] = __floats2half2_rn(v.z, v.w);
}

__global__ __launch_bounds__(256) void split_w4_kernel(
    const float* __restrict__ w0, const float* __restrict__ w1,
    const float* __restrict__ w2, const float* __restrict__ w3,
    __half* __restrict__ hi, int n4)
{
    const int z = blockIdx.y;
    const float* w = (z == 0) ? w0 : ((z == 1) ? w1 : ((z == 2) ? w2 : w3));
    int i = blockIdx.x * blockDim.x + threadIdx.x;
    if (i >= n4) return;
    float4 v = ((const float4*)w)[i];
    __half2* hp = (__half2*)(hi + (size_t)z * n4 * 4 + (size_t)i * 4);
    hp[0] = __floats2half2_rn(v.x, v.y);
    hp[1] = __floats2half2_rn(v.z, v.w);
}

// ---------------------------------------------------------------------------
// GEMM: CTA 128x128, 256 thr (8 warps, 2M x 4N), BK=64, 3-stage cp.async.
// Pure fp16: C = Ah * Wh (fp32 acc). Stage = {Ah, Wh}.
// ---------------------------------------------------------------------------
#define BK 64
#define NKC (DD / BK)
#define TSTRIDE 72
#define TILE_B (128 * TSTRIDE * 2)   // 18432
#define STAGE_B (2 * TILE_B)         // 36864
#define NSTAGE 3
#define GEMM_SMEM (NSTAGE * STAGE_B) // 110592

__device__ __forceinline__ void load_tile_async(
    uint32_t sbase, const __half* __restrict__ src,
    int row_base, int k0, int tid)
{
#pragma unroll
    for (int p = 0; p < 4; p++) {
        const int i = p * 256 + tid;
        const int r = i >> 3;
        const int c = i & 7;
        cp16(sbase + r * (TSTRIDE * 2) + c * 16,
             src + (size_t)(row_base + r) * DD + k0 + c * 8);
    }
}

__device__ __forceinline__ void load_stage(
    uint32_t sbase, const __half* Ahi, const __half* Whi,
    int bm, int bn, int k0, int tid)
{
    load_tile_async(sbase + 0 * TILE_B, Ahi, bm, k0, tid);
    load_tile_async(sbase + 1 * TILE_B, Whi, bn, k0, tid);
    cp_commit();
}

__device__ __forceinline__ void gemm_mainloop(
    char* sm, uint32_t sb,
    const __half* Ahi, const __half* Whi,
    int bm, int bn, int tid, int wm, int wn, int g, int t,
    float acc[4][4][4])
{
    load_stage(sb + 0 * STAGE_B, Ahi, Whi, bm, bn, 0, tid);
    load_stage(sb + 1 * STAGE_B, Ahi, Whi, bm, bn, BK, tid);

    for (int kc = 0; kc < NKC; kc++) {
        if (kc + 2 < NKC) {
            load_stage(sb + ((kc + 2) % NSTAGE) * STAGE_B,
                       Ahi, Whi, bm, bn, (kc + 2) * BK, tid);
            cp_wait<2>();
        } else if (kc + 1 < NKC) {
            cp_wait<1>();
        } else {
            cp_wait<0>();
        }
        __syncthreads();

        const char* stg = sm + (kc % NSTAGE) * STAGE_B;
        const char* tAhi = stg + 0 * TILE_B;
        const char* tWhi = stg + 1 * TILE_B;

#pragma unroll
        for (int k16 = 0; k16 < 4; k16++) {
            const int k0 = k16 * 16;
            uint32_t ah[4][4], bh[4][2];
#pragma unroll
            for (int mt = 0; mt < 4; mt++) {
                const int r0 = wm + mt * 16 + g;
                const int cA = k0 + 2 * t;
                ah[mt][0] = *(const uint32_t*)(tAhi + ((r0)     * TSTRIDE + cA)     * 2);
                ah[mt][1] = *(const uint32_t*)(tAhi + ((r0 + 8) * TSTRIDE + cA)     * 2);
                ah[mt][2] = *(const uint32_t*)(tAhi + ((r0)     * TSTRIDE + cA + 8) * 2);
                ah[mt][3] = *(const uint32_t*)(tAhi + ((r0 + 8) * TSTRIDE + cA + 8) * 2);
            }
#pragma unroll
            for (int nt = 0; nt < 4; nt++) {
                const int nr = wn + nt * 8 + g;
                const int cB = k0 + 2 * t;
                bh[nt][0] = *(const uint32_t*)(tWhi + (nr * TSTRIDE + cB)     * 2);
                bh[nt][1] = *(const uint32_t*)(tWhi + (nr * TSTRIDE + cB + 8) * 2);
            }
#pragma unroll
            for (int mt = 0; mt < 4; mt++)
#pragma unroll
                for (int nt = 0; nt < 4; nt++) {
                    float* c = acc[mt][nt];
                    mma_f16(c[0], c[1], c[2], c[3],
                            ah[mt][0], ah[mt][1], ah[mt][2], ah[mt][3],
                            bh[nt][0], bh[nt][1]);
                }
        }
        __syncthreads();
    }
}

// fused QKV projection GEMM: gridDim.z selects {Q, K, V}; fp16 outputs
__global__ __launch_bounds__(256) void qkv_gemm_kernel(
    const __half* __restrict__ xhi, const __half* __restrict__ whi,
    const float* __restrict__ bq, const float* __restrict__ bk,
    const float* __restrict__ bv,
    __half* __restrict__ qh, __half* __restrict__ kh,
    __half* __restrict__ vth)
{
    extern __shared__ char sm[];
    const uint32_t sb = smem_u32(sm);
    const int tid = threadIdx.x;
    const int wid = tid >> 5;
    const int lid = tid & 31;
    const int g = lid >> 2;
    const int t = lid & 3;
    const int bm = blockIdx.y * 128;
    const int bn = blockIdx.x * 128;
    const int wm = (wid & 1) * 64;
    const int wn = (wid >> 1) * 32;
    const int z = blockIdx.z;

    const size_t Msz = (size_t)BB * SS * DD;
    const __half* Ahi = xhi + (size_t)z * Msz;
    const __half* Whi = whi + (size_t)z * DD * DD;
    const float* bias = (z == 0) ? bq : ((z == 1) ? bk : bv);
    __half* Oh = (z == 0) ? qh : ((z == 1) ? kh : vth);

    float acc[4][4][4];
#pragma unroll
    for (int mt = 0; mt < 4; mt++)
#pragma unroll
        for (int nt = 0; nt < 4; nt++)
#pragma unroll
            for (int r = 0; r < 4; r++) acc[mt][nt][r] = 0.0f;

    gemm_mainloop(sm, sb, Ahi, Whi, bm, bn, tid, wm, wn, g, t, acc);

    const bool trans = (z == 2);
#pragma unroll
    for (int mt = 0; mt < 4; mt++) {
#pragma unroll
        for (int nt = 0; nt < 4; nt++) {
            const float* c = acc[mt][nt];
            const int n0 = bn + wn + nt * 8 + 2 * t;
            const float bia0 = __ldg(&bias[n0]);
            const float bia1 = __ldg(&bias[n0 + 1]);
#pragma unroll
            for (int half = 0; half < 2; half++) {
                const int m = bm + wm + mt * 16 + g + half * 8;
                const float v0 = c[half * 2 + 0] + bia0;
                const float v1 = c[half * 2 + 1] + bia1;
                const int bidx = m >> 11;
                const int sidx = m & (SS - 1);
                const int h0 = n0 >> 6;
                const int dh = n0 & (DHH - 1);
                if (!trans) {
                    const size_t idx = (((size_t)bidx * HH + h0) * SS + sidx) * DHH + dh;
                    *(__half2*)(Oh + idx) = __floats2half2_rn(v0, v1);
                } else {
                    const size_t idx = (((size_t)bidx * HH + h0) * DHH + dh) * SS + sidx;
                    Oh[idx] = __float2half_rn(v0);
                    Oh[idx + SS] = __float2half_rn(v1);
                }
            }
        }
    }
}

// O projection GEMM (fp32 row-major out)
__global__ __launch_bounds__(256) void o_gemm_kernel(
    const __half* __restrict__ Ahi, const __half* __restrict__ Whi,
    const float* __restrict__ bias, float* __restrict__ C)
{
    extern __shared__ char sm[];
    const uint32_t sb = smem_u32(sm);
    const int tid = threadIdx.x;
    const int wid = tid >> 5;
    const int lid = tid & 31;
    const int g = lid >> 2;
    const int t = lid & 3;
    const int bm = blockIdx.y * 128;
    const int bn = blockIdx.x * 128;
    const int wm = (wid & 1) * 64;
    const int wn = (wid >> 1) * 32;

    float acc[4][4][4];
#pragma unroll
    for (int mt = 0; mt < 4; mt++)
#pragma unroll
        for (int nt = 0; nt < 4; nt++)
#pragma unroll
            for (int r = 0; r < 4; r++) acc[mt][nt][r] = 0.0f;

    gemm_mainloop(sm, sb, Ahi, Whi, bm, bn, tid, wm, wn, g, t, acc);

#pragma unroll
    for (int mt = 0; mt < 4; mt++) {
#pragma unroll
        for (int nt = 0; nt < 4; nt++) {
            const float* c = acc[mt][nt];
            const int n0 = bn + wn + nt * 8 + 2 * t;
            const float bia0 = __ldg(&bias[n0]);
            const float bia1 = __ldg(&bias[n0 + 1]);
#pragma unroll
            for (int half = 0; half < 2; half++) {
                const int m = bm + wm + mt * 16 + g + half * 8;
                C[(size_t)m * DD + n0]     = c[half * 2 + 0] + bia0;
                C[(size_t)m * DD + n0 + 1] = c[half * 2 + 1] + bia1;
            }
        }
    }
}

// ---------------------------------------------------------------------------
// Tensor-core flash attention, pure fp16 (unchanged from R11)
// ---------------------------------------------------------------------------
#define KSTR 72
#define FTILE_B (64 * KSTR * 2)
#define FSTAGE_B (2 * FTILE_B)
#define FLASH_SMEM (2 * FSTAGE_B)

__global__ __launch_bounds__(128) void flash_tc_kernel(
    const __half* __restrict__ Qh,
    const __half* __restrict__ Kh,
    const __half* __restrict__ VTh,
    __half* __restrict__ Ctx)
{
    extern __shared__ char sm[];
    const uint32_t sb = smem_u32(sm);
    const int tid = threadIdx.x;
    const int wid = tid >> 5;
    const int lid = tid & 31;
    const int g = lid >> 2;
    const int t = lid & 3;
    const int qb = gridDim.x - 1 - blockIdx.x;
    const int bh = blockIdx.y;

    const size_t hoff = (size_t)bh * SS * DHH;
    const __half* qh = Qh + hoff;
    const __half* kh = Kh + hoff;
    const __half* vth = VTh + hoff;

    const int qrow0 = qb * 64 + wid * 16;

    uint32_t qf[4][4];
#pragma unroll
    for (int s = 0; s < 4; s++) {
        const int cA = s * 16 + 2 * t;
        qf[s][0] = *(const uint32_t*)(qh + (size_t)(qrow0 + g)     * DHH + cA);
        qf[s][1] = *(const uint32_t*)(qh + (size_t)(qrow0 + g + 8) * DHH + cA);
        qf[s][2] = *(const uint32_t*)(qh + (size_t)(qrow0 + g)     * DHH + cA + 8);
        qf[s][3] = *(const uint32_t*)(qh + (size_t)(qrow0 + g + 8) * DHH + cA + 8);
    }

    float oa[8][4];
#pragma unroll
    for (int j = 0; j < 8; j++)
#pragma unroll
        for (int r = 0; r < 4; r++) oa[j][r] = 0.0f;
    float mrun0 = -INFINITY, mrun1 = -INFINITY, lrun0 = 0.0f, lrun1 = 0.0f;

    auto load_kv = [&](int jb, int stage) {
        const uint32_t s0 = sb + stage * FSTAGE_B;
        const int kb = jb * 64;
#pragma unroll
        for (int p = 0; p < 4; p++) {
            const int i = p * 128 + tid;
            const int r = i >> 3;
            const int c = i & 7;
            const uint32_t d = r * (KSTR * 2) + c * 16;
            cp16(s0 + 0 * FTILE_B + d, kh  + (size_t)(kb + r) * DHH + c * 8);
            cp16(s0 + 1 * FTILE_B + d, vth + (size_t)r * SS + kb + c * 8);
        }
    };

    load_kv(0, 0);
    cp_commit();

    const float scale = 0.125f;

    for (int jb = 0; jb <= qb; jb++) {
        const int s = jb & 1;
        if (jb < qb) {
            load_kv(jb + 1, s ^ 1);
            cp_commit();
            cp_wait<1>();
        } else {
            cp_wait<0>();
        }
        __syncthreads();

        const char* stg = sm + s * FSTAGE_B;
        const char* tKh = stg + 0 * FTILE_B;
        const char* tVh = stg + 1 * FTILE_B;

        float sacc[8][4];
#pragma unroll
        for (int j = 0; j < 8; j++)
#pragma unroll
            for (int r = 0; r < 4; r++) sacc[j][r] = 0.0f;

#pragma unroll
        for (int ks = 0; ks < 4; ks++) {
            const int cB = ks * 16 + 2 * t;
            uint32_t kb0[8], kb1[8];
#pragma unroll
            for (int j = 0; j < 8; j++) {
                const int nr = j * 8 + g;
                kb0[j] = *(const uint32_t*)(tKh + (nr * KSTR + cB)     * 2);
                kb1[j] = *(const uint32_t*)(tKh + (nr * KSTR + cB + 8) * 2);
            }
#pragma unroll
            for (int j = 0; j < 8; j++)
                mma_f16(sacc[j][0], sacc[j][1], sacc[j][2], sacc[j][3],
                        qf[ks][0], qf[ks][1], qf[ks][2], qf[ks][3],
                        kb0[j], kb1[j]);
        }

        const int qg0 = qrow0 + g;
        const int qg1 = qrow0 + g + 8;
        if (jb == qb) {
            const int kbase = jb * 64;
#pragma unroll
            for (int j = 0; j < 8; j++) {
                const int c0 = kbase + j * 8 + 2 * t;
                const int c1 = c0 + 1;
                sacc[j][0] = (c0 > qg0) ? -1e30f : sacc[j][0] * scale;
                sacc[j][1] = (c1 > qg0) ? -1e30f : sacc[j][1] * scale;
                sacc[j][2] = (c0 > qg1) ? -1e30f : sacc[j][2] * scale;
                sacc[j][3] = (c1 > qg1) ? -1e30f : sacc[j][3] * scale;
            }
        } else {
#pragma unroll
            for (int j = 0; j < 8; j++)
#pragma unroll
                for (int r = 0; r < 4; r++) sacc[j][r] *= scale;
        }

        float mt0 = -INFINITY, mt1 = -INFINITY;
#pragma unroll
        for (int j = 0; j < 8; j++) {
            mt0 = fmaxf(mt0, fmaxf(sacc[j][0], sacc[j][1]));
            mt1 = fmaxf(mt1, fmaxf(sacc[j][2], sacc[j][3]));
        }
        mt0 = fmaxf(mt0, __shfl_xor_sync(0xffffffffu, mt0, 1));
        mt0 = fmaxf(mt0, __shfl_xor_sync(0xffffffffu, mt0, 2));
        mt1 = fmaxf(mt1, __shfl_xor_sync(0xffffffffu, mt1, 1));
        mt1 = fmaxf(mt1, __shfl_xor_sync(0xffffffffu, mt1, 2));
        const float mn0 = fmaxf(mrun0, mt0);
        const float mn1 = fmaxf(mrun1, mt1);
        const float al0 = __expf(mrun0 - mn0);
        const float al1 = __expf(mrun1 - mn1);
        float rs0 = 0.0f, rs1 = 0.0f;
#pragma unroll
        for (int j = 0; j < 8; j++) {
            sacc[j][0] = __expf(sacc[j][0] - mn0);
            sacc[j][1] = __expf(sacc[j][1] - mn0);
            sacc[j][2] = __expf(sacc[j][2] - mn1);
            sacc[j][3] = __expf(sacc[j][3] - mn1);
            rs0 += sacc[j][0] + sacc[j][1];
            rs1 += sacc[j][2] + sacc[j][3];
        }
        rs0 += __shfl_xor_sync(0xffffffffu, rs0, 1);
        rs0 += __shfl_xor_sync(0xffffffffu, rs0, 2);
        rs1 += __shfl_xor_sync(0xffffffffu, rs1, 1);
        rs1 += __shfl_xor_sync(0xffffffffu, rs1, 2);
        lrun0 = al0 * lrun0 + rs0;
        lrun1 = al1 * lrun1 + rs1;
        mrun0 = mn0;
        mrun1 = mn1;
#pragma unroll
        for (int j = 0; j < 8; j++) {
            oa[j][0] *= al0;
            oa[j][1] *= al0;
            oa[j][2] *= al1;
            oa[j][3] *= al1;
        }

#pragma unroll
        for (int ks = 0; ks < 4; ks++) {
            const int j0 = 2 * ks, j1 = 2 * ks + 1;
            uint32_t pah[4];
            pah[0] = pack_f16x2(sacc[j0][0], sacc[j0][1]);
            pah[1] = pack_f16x2(sacc[j0][2], sacc[j0][3]);
            pah[2] = pack_f16x2(sacc[j1][0], sacc[j1][1]);
            pah[3] = pack_f16x2(sacc[j1][2], sacc[j1][3]);

            uint32_t vb0[8], vb1[8];
#pragma unroll
            for (int jd = 0; jd < 8; jd++) {
                const int nr = jd * 8 + g;
                const int cB = ks * 16 + 2 * t;
                vb0[jd] = *(const uint32_t*)(tVh + (nr * KSTR + cB)     * 2);
                vb1[jd] = *(const uint32_t*)(tVh + (nr * KSTR + cB + 8) * 2);
            }
#pragma unroll
            for (int jd = 0; jd < 8; jd++)
                mma_f16(oa[jd][0], oa[jd][1], oa[jd][2], oa[jd][3],
                        pah[0], pah[1], pah[2], pah[3], vb0[jd], vb1[jd]);
        }
        __syncthreads();
    }

    const int b = bh >> 4;
    const int h = bh & 15;
    const float inv0 = 1.0f / lrun0;
    const float inv1 = 1.0f / lrun1;
#pragma unroll
    for (int jd = 0; jd < 8; jd++) {
        const int dh = jd * 8 + 2 * t;
        const size_t idx0 = ((size_t)b * SS + qrow0 + g)     * DD + h * DHH + dh;
        const size_t idx1 = ((size_t)b * SS + qrow0 + g + 8) * DD + h * DHH + dh;
        *(__half2*)(Ctx + idx0) =
            __floats2half2_rn(oa[jd][0] * inv0, oa[jd][1] * inv0);
        *(__half2*)(Ctx + idx1) =
            __floats2half2_rn(oa[jd][2] * inv1, oa[jd][3] * inv1);
    }
}

// ---------------------------------------------------------------------------
// Launch
// ---------------------------------------------------------------------------
extern "C" void kernel_launch(void* const* d_in, const int* in_sizes, int n_in,
                              void* d_out, int out_size)
{
    const float* query = (const float*)d_in[0];
    const float* key_i = (const float*)d_in[1];
    const float* value = (const float*)d_in[2];
    const float* Wq = (const float*)d_in[4];
    const float* bq = (const float*)d_in[5];
    const float* Wk = (const float*)d_in[6];
    const float* bk = (const float*)d_in[7];
    const float* Wv = (const float*)d_in[8];
    const float* bv = (const float*)d_in[9];
    const float* Wo = (const float*)d_in[10];
    const float* bo = (const float*)d_in[11];
    float* out = (float*)d_out;

    __half *xhi, *whi, *qh, *kh, *vth;
    cudaGetSymbolAddress((void**)&xhi, g_xhi);
    cudaGetSymbolAddress((void**)&whi, g_whi);
    cudaGetSymbolAddress((void**)&qh, g_qh);
    cudaGetSymbolAddress((void**)&kh, g_kh);
    cudaGetSymbolAddress((void**)&vth, g_vth);

    const int M = BB * SS;
    const int nX4 = M * DD / 4;
    const int nW4 = DD * DD / 4;

    cudaFuncSetAttribute(qkv_gemm_kernel,
                         cudaFuncAttributeMaxDynamicSharedMemorySize, GEMM_SMEM);
    cudaFuncSetAttribute(o_gemm_kernel,
                         cudaFuncAttributeMaxDynamicSharedMemorySize, GEMM_SMEM);
    cudaFuncSetAttribute(flash_tc_kernel,
                         cudaFuncAttributeMaxDynamicSharedMemorySize, FLASH_SMEM);

    // splits (fp16)
    split_x3_kernel<<<dim3((nX4 + 255) / 256, 3), 256>>>(
        query, key_i, value, xhi, nX4);
    split_w4_kernel<<<dim3((nW4 + 255) / 256, 4), 256>>>(
        Wq, Wk, Wv, Wo, whi, nW4);

    // fused QKV projections (z = 0,1,2)
    qkv_gemm_kernel<<<dim3(DD / 128, M / 128, 3), 256, GEMM_SMEM>>>(
        xhi, whi, bq, bk, bv, qh, kh, vth);

    // flash attention -> ctx fp16 into xhi slot 0
    flash_tc_kernel<<<dim3(SS / 64, BB * HH), 128, FLASH_SMEM>>>(
        qh, kh, vth, xhi);

    // O projection
    o_gemm_kernel<<<dim3(DD / 128, M / 128), 256, GEMM_SMEM>>>(
        xhi, whi + (size_t)3 * DD * DD, bo, out);
}